// round 1
// baseline (speedup 1.0000x reference)
#include <cuda_runtime.h>
#include <math.h>

#define TB 2
#define TT 2048
#define TC 1024
#define NH 16
#define HD 64
#define BHN (TB*NH)
#define MROWS (TB*TT)
#define SCALE 0.125f

// Scratch (static device allocations; allowed by harness rules)
__device__ float g_q[(size_t)BHN*TT*HD];
__device__ float g_k[(size_t)BHN*TT*HD];
__device__ float g_k2[(size_t)BHN*TT*HD];
__device__ float g_y[(size_t)BHN*TT*HD];
__device__ float g_ysum[(size_t)TB*TT*TC];

// ---------------------------------------------------------------------------
// SGEMM: 128x128 block tile, BK=16, 256 threads, 8x8 per thread.
// MODE 0: C = x @ W_attn  -> scatter to g_q (n<C) / g_k (n>=C) in head layout
// MODE 1: C = x @ W_k2    -> scatter to g_k2 in head layout
// MODE 2: C = g_ysum @ W_proj -> row-major Cout (d_out)
// ---------------------------------------------------------------------------
template<int MODE>
__global__ __launch_bounds__(256)
void sgemm_kernel(const float* __restrict__ A, const float* __restrict__ Bw,
                  float* __restrict__ Cout, int M, int N, int K)
{
    __shared__ float As[16][128];
    __shared__ float Bs[16][128];
    const int tid = threadIdx.x;
    const int bm = blockIdx.y * 128;
    const int bn = blockIdx.x * 128;
    const float* Ap = (MODE == 2) ? (const float*)g_ysum : A;

    float acc[8][8];
#pragma unroll
    for (int i = 0; i < 8; i++)
#pragma unroll
        for (int j = 0; j < 8; j++) acc[i][j] = 0.f;

    const int tr = tid >> 4, tc = tid & 15;

    for (int kt = 0; kt < K; kt += 16) {
#pragma unroll
        for (int l = 0; l < 2; l++) {
            int idx = tid + l * 256;
            int aRow = idx >> 2, aq = (idx & 3) << 2;
            float4 av = *(const float4*)(Ap + (size_t)(bm + aRow) * K + kt + aq);
            As[aq + 0][aRow] = av.x;
            As[aq + 1][aRow] = av.y;
            As[aq + 2][aRow] = av.z;
            As[aq + 3][aRow] = av.w;
            int bRow = idx >> 5, bc = (idx & 31) << 2;
            *(float4*)&Bs[bRow][bc] =
                *(const float4*)(Bw + (size_t)(kt + bRow) * N + bn + bc);
        }
        __syncthreads();
#pragma unroll
        for (int k = 0; k < 16; k++) {
            float a[8], b[8];
#pragma unroll
            for (int i = 0; i < 8; i++) a[i] = As[k][tr * 8 + i];
#pragma unroll
            for (int j = 0; j < 8; j++) b[j] = Bs[k][tc * 8 + j];
#pragma unroll
            for (int i = 0; i < 8; i++)
#pragma unroll
                for (int j = 0; j < 8; j++) acc[i][j] += a[i] * b[j];
        }
        __syncthreads();
    }

#pragma unroll
    for (int i = 0; i < 8; i++) {
        int m = bm + tr * 8 + i;
        int b = m >> 11;             // /T (2048)
        int t = m & (TT - 1);
#pragma unroll
        for (int jq = 0; jq < 8; jq += 4) {
            int n = bn + tc * 8 + jq;
            float4 v = make_float4(acc[i][jq], acc[i][jq + 1],
                                   acc[i][jq + 2], acc[i][jq + 3]);
            if (MODE == 2) {
                *(float4*)(Cout + (size_t)m * N + n) = v;
            } else if (MODE == 0) {
                float* base = g_q;
                int nn = n;
                if (nn >= TC) { nn -= TC; base = g_k; }
                int h = nn >> 6, dd = nn & 63;
                *(float4*)(base + (((size_t)(b * NH + h) * TT + t) << 6) + dd) = v;
            } else {
                int h = n >> 6, dd = n & 63;
                *(float4*)(g_k2 + (((size_t)(b * NH + h) * TT + t) << 6) + dd) = v;
            }
        }
    }
}

// ---------------------------------------------------------------------------
// Flash attention (causal softmax). 64x64 tiles, 256 threads (16x16),
// each thread holds a 4x4 score fragment and 4x64-col slice of output (4x4).
// smem: Qs,Ks,Vs,Ps each 64x68 (pad 4 floats -> conflict-free float4 access)
// ---------------------------------------------------------------------------
__global__ __launch_bounds__(256)
void attn1_kernel(const float* __restrict__ x)
{
    extern __shared__ float sm[];
    float* Qs = sm;
    float* Ks = sm + 64 * 68;
    float* Vs = sm + 2 * 64 * 68;
    float* Ps = sm + 3 * 64 * 68;

    const int tid = threadIdx.x;
    const int bh = blockIdx.y;
    const int b = bh >> 4, h = bh & 15;
    const int q0 = blockIdx.x * 64;
    const float* qptr = g_q + (size_t)bh * TT * HD;
    const float* kptr = g_k + (size_t)bh * TT * HD;
    const float* vptr = x + (size_t)b * TT * TC + h * HD;   // row stride TC

    // Load Q tile, pre-scaled
#pragma unroll
    for (int l = 0; l < 4; l++) {
        int idx = tid + l * 256;
        int row = idx >> 4, cq = (idx & 15) << 2;
        float4 v = *(const float4*)(qptr + (size_t)(q0 + row) * HD + cq);
        float* d = Qs + row * 68 + cq;
        d[0] = v.x * SCALE; d[1] = v.y * SCALE;
        d[2] = v.z * SCALE; d[3] = v.w * SCALE;
    }

    const int tr = tid >> 4, tc = tid & 15;
    float m_run[4], l_run[4], O[4][4];
#pragma unroll
    for (int i = 0; i < 4; i++) {
        m_run[i] = -1e30f; l_run[i] = 0.f;
#pragma unroll
        for (int j = 0; j < 4; j++) O[i][j] = 0.f;
    }

    const int ntiles = blockIdx.x + 1;
    for (int kt = 0; kt < ntiles; kt++) {
        const int s0 = kt * 64;
        __syncthreads();   // previous iteration finished with Ks/Vs/Ps
#pragma unroll
        for (int l = 0; l < 4; l++) {
            int idx = tid + l * 256;
            int row = idx >> 4, cq = (idx & 15) << 2;
            *(float4*)(Ks + row * 68 + cq) =
                *(const float4*)(kptr + (size_t)(s0 + row) * HD + cq);
            *(float4*)(Vs + row * 68 + cq) =
                *(const float4*)(vptr + (size_t)(s0 + row) * TC + cq);
        }
        __syncthreads();

        float S[4][4];
#pragma unroll
        for (int i = 0; i < 4; i++)
#pragma unroll
            for (int j = 0; j < 4; j++) S[i][j] = 0.f;

#pragma unroll
        for (int d0 = 0; d0 < HD; d0 += 4) {
            float qv[4][4], kv[4][4];
#pragma unroll
            for (int i = 0; i < 4; i++) {
                float4 t4 = *(const float4*)(Qs + (tr * 4 + i) * 68 + d0);
                qv[i][0] = t4.x; qv[i][1] = t4.y; qv[i][2] = t4.z; qv[i][3] = t4.w;
            }
#pragma unroll
            for (int j = 0; j < 4; j++) {
                float4 t4 = *(const float4*)(Ks + (tc * 4 + j) * 68 + d0);
                kv[j][0] = t4.x; kv[j][1] = t4.y; kv[j][2] = t4.z; kv[j][3] = t4.w;
            }
#pragma unroll
            for (int i = 0; i < 4; i++)
#pragma unroll
                for (int j = 0; j < 4; j++)
#pragma unroll
                    for (int dd = 0; dd < 4; dd++)
                        S[i][j] += qv[i][dd] * kv[j][dd];
        }

        if (kt == blockIdx.x) {  // diagonal tile: key > query -> -inf
#pragma unroll
            for (int i = 0; i < 4; i++)
#pragma unroll
                for (int j = 0; j < 4; j++)
                    if (tc * 4 + j > tr * 4 + i) S[i][j] = -1e30f;
        }

        float mt[4];
#pragma unroll
        for (int i = 0; i < 4; i++)
            mt[i] = fmaxf(fmaxf(S[i][0], S[i][1]), fmaxf(S[i][2], S[i][3]));
#pragma unroll
        for (int off = 8; off > 0; off >>= 1)
#pragma unroll
            for (int i = 0; i < 4; i++)
                mt[i] = fmaxf(mt[i], __shfl_xor_sync(0xffffffffu, mt[i], off));

        float corr[4];
#pragma unroll
        for (int i = 0; i < 4; i++) {
            float mn = fmaxf(m_run[i], mt[i]);
            corr[i] = __expf(m_run[i] - mn);
            m_run[i] = mn;
        }
        float rs[4];
#pragma unroll
        for (int i = 0; i < 4; i++) {
            float r = 0.f;
#pragma unroll
            for (int j = 0; j < 4; j++) {
                S[i][j] = __expf(S[i][j] - m_run[i]);
                r += S[i][j];
            }
            rs[i] = r;
        }
#pragma unroll
        for (int off = 8; off > 0; off >>= 1)
#pragma unroll
            for (int i = 0; i < 4; i++)
                rs[i] += __shfl_xor_sync(0xffffffffu, rs[i], off);
#pragma unroll
        for (int i = 0; i < 4; i++) {
            l_run[i] = l_run[i] * corr[i] + rs[i];
#pragma unroll
            for (int j = 0; j < 4; j++) O[i][j] *= corr[i];
        }
        // stage P
#pragma unroll
        for (int i = 0; i < 4; i++)
            *(float4*)(Ps + (tr * 4 + i) * 68 + tc * 4) =
                make_float4(S[i][0], S[i][1], S[i][2], S[i][3]);
        __syncthreads();

        // O += P @ V
#pragma unroll
        for (int j0 = 0; j0 < 64; j0 += 4) {
            float pv[4][4];
#pragma unroll
            for (int i = 0; i < 4; i++) {
                float4 t4 = *(const float4*)(Ps + (tr * 4 + i) * 68 + j0);
                pv[i][0] = t4.x; pv[i][1] = t4.y; pv[i][2] = t4.z; pv[i][3] = t4.w;
            }
#pragma unroll
            for (int jj = 0; jj < 4; jj++) {
                float4 vv = *(const float4*)(Vs + (j0 + jj) * 68 + tc * 4);
#pragma unroll
                for (int i = 0; i < 4; i++) {
                    O[i][0] += pv[i][jj] * vv.x;
                    O[i][1] += pv[i][jj] * vv.y;
                    O[i][2] += pv[i][jj] * vv.z;
                    O[i][3] += pv[i][jj] * vv.w;
                }
            }
        }
    }

    float* ybase = g_y + (size_t)bh * TT * HD;
#pragma unroll
    for (int i = 0; i < 4; i++) {
        float inv = 1.f / l_run[i];
        *(float4*)(ybase + (size_t)(q0 + tr * 4 + i) * HD + tc * 4) =
            make_float4(O[i][0] * inv, O[i][1] * inv, O[i][2] * inv, O[i][3] * inv);
    }
}

// ---------------------------------------------------------------------------
// ARMA attention (no softmax), strict-lower causal mask.
// y2[r] = sum_{s<r} (qa[r].ka[s]) * e[s],  e[s] = x_head[s+1] - y[s]
// qa = min(qs, 0.02*qs) with qs = q*SCALE;  ka = sigmoid(0.0025 * k2)
// Writes g_ysum = merge(y) + merge(y2).
// ---------------------------------------------------------------------------
__global__ __launch_bounds__(256)
void attn2_kernel(const float* __restrict__ x)
{
    extern __shared__ float sm[];
    float* Qs = sm;
    float* Ks = sm + 64 * 68;
    float* Es = sm + 2 * 64 * 68;
    float* Ps = sm + 3 * 64 * 68;

    const int tid = threadIdx.x;
    const int bh = blockIdx.y;
    const int b = bh >> 4, h = bh & 15;
    const int q0 = blockIdx.x * 64;
    const float* qptr = g_q + (size_t)bh * TT * HD;
    const float* k2ptr = g_k2 + (size_t)bh * TT * HD;
    const float* ybase = g_y + (size_t)bh * TT * HD;
    const float* vptr = x + (size_t)b * TT * TC + h * HD;

    // Load qa tile
#pragma unroll
    for (int l = 0; l < 4; l++) {
        int idx = tid + l * 256;
        int row = idx >> 4, cq = (idx & 15) << 2;
        float4 v = *(const float4*)(qptr + (size_t)(q0 + row) * HD + cq);
        float* d = Qs + row * 68 + cq;
        float q0v = v.x * SCALE, q1v = v.y * SCALE, q2v = v.z * SCALE, q3v = v.w * SCALE;
        d[0] = fminf(q0v, 0.02f * q0v);
        d[1] = fminf(q1v, 0.02f * q1v);
        d[2] = fminf(q2v, 0.02f * q2v);
        d[3] = fminf(q3v, 0.02f * q3v);
    }

    const int tr = tid >> 4, tc = tid & 15;
    float O[4][4];
#pragma unroll
    for (int i = 0; i < 4; i++)
#pragma unroll
        for (int j = 0; j < 4; j++) O[i][j] = 0.f;

    const int ntiles = blockIdx.x + 1;
    for (int kt = 0; kt < ntiles; kt++) {
        const int s0 = kt * 64;
        __syncthreads();
#pragma unroll
        for (int l = 0; l < 4; l++) {
            int idx = tid + l * 256;
            int row = idx >> 4, cq = (idx & 15) << 2;
            int s = s0 + row;
            float4 kv = *(const float4*)(k2ptr + (size_t)s * HD + cq);
            float* kd = Ks + row * 68 + cq;
            kd[0] = 1.f / (1.f + __expf(-0.0025f * kv.x));
            kd[1] = 1.f / (1.f + __expf(-0.0025f * kv.y));
            kd[2] = 1.f / (1.f + __expf(-0.0025f * kv.z));
            kd[3] = 1.f / (1.f + __expf(-0.0025f * kv.w));
            float* ed = Es + row * 68 + cq;
            if (s + 1 < TT) {
                float4 xv = *(const float4*)(vptr + (size_t)(s + 1) * TC + cq);
                float4 yv = *(const float4*)(ybase + (size_t)s * HD + cq);
                ed[0] = xv.x - yv.x; ed[1] = xv.y - yv.y;
                ed[2] = xv.z - yv.z; ed[3] = xv.w - yv.w;
            } else {
                ed[0] = 0.f; ed[1] = 0.f; ed[2] = 0.f; ed[3] = 0.f;
            }
        }
        __syncthreads();

        float S[4][4];
#pragma unroll
        for (int i = 0; i < 4; i++)
#pragma unroll
            for (int j = 0; j < 4; j++) S[i][j] = 0.f;

#pragma unroll
        for (int d0 = 0; d0 < HD; d0 += 4) {
            float qv[4][4], kv[4][4];
#pragma unroll
            for (int i = 0; i < 4; i++) {
                float4 t4 = *(const float4*)(Qs + (tr * 4 + i) * 68 + d0);
                qv[i][0] = t4.x; qv[i][1] = t4.y; qv[i][2] = t4.z; qv[i][3] = t4.w;
            }
#pragma unroll
            for (int j = 0; j < 4; j++) {
                float4 t4 = *(const float4*)(Ks + (tc * 4 + j) * 68 + d0);
                kv[j][0] = t4.x; kv[j][1] = t4.y; kv[j][2] = t4.z; kv[j][3] = t4.w;
            }
#pragma unroll
            for (int i = 0; i < 4; i++)
#pragma unroll
                for (int j = 0; j < 4; j++)
#pragma unroll
                    for (int dd = 0; dd < 4; dd++)
                        S[i][j] += qv[i][dd] * kv[j][dd];
        }

        if (kt == blockIdx.x) {  // diagonal tile: keep strictly lower (s < r)
#pragma unroll
            for (int i = 0; i < 4; i++)
#pragma unroll
                for (int j = 0; j < 4; j++)
                    if (!(tc * 4 + j < tr * 4 + i)) S[i][j] = 0.f;
        }

#pragma unroll
        for (int i = 0; i < 4; i++)
            *(float4*)(Ps + (tr * 4 + i) * 68 + tc * 4) =
                make_float4(S[i][0], S[i][1], S[i][2], S[i][3]);
        __syncthreads();

#pragma unroll
        for (int j0 = 0; j0 < 64; j0 += 4) {
            float pv[4][4];
#pragma unroll
            for (int i = 0; i < 4; i++) {
                float4 t4 = *(const float4*)(Ps + (tr * 4 + i) * 68 + j0);
                pv[i][0] = t4.x; pv[i][1] = t4.y; pv[i][2] = t4.z; pv[i][3] = t4.w;
            }
#pragma unroll
            for (int jj = 0; jj < 4; jj++) {
                float4 vv = *(const float4*)(Es + (j0 + jj) * 68 + tc * 4);
#pragma unroll
                for (int i = 0; i < 4; i++) {
                    O[i][0] += pv[i][jj] * vv.x;
                    O[i][1] += pv[i][jj] * vv.y;
                    O[i][2] += pv[i][jj] * vv.z;
                    O[i][3] += pv[i][jj] * vv.w;
                }
            }
        }
    }

    // ysum = merge(y) + merge(y2)
#pragma unroll
    for (int i = 0; i < 4; i++) {
        int r = q0 + tr * 4 + i;
        float4 yv = *(const float4*)(ybase + (size_t)r * HD + tc * 4);
        *(float4*)(g_ysum + ((size_t)b * TT + r) * TC + h * HD + tc * 4) =
            make_float4(O[i][0] + yv.x, O[i][1] + yv.y,
                        O[i][2] + yv.z, O[i][3] + yv.w);
    }
}

// ---------------------------------------------------------------------------
extern "C" void kernel_launch(void* const* d_in, const int* in_sizes, int n_in,
                              void* d_out, int out_size)
{
    (void)in_sizes; (void)n_in; (void)out_size;
    const float* x      = (const float*)d_in[0];
    const float* W_attn = (const float*)d_in[1];
    const float* W_k2   = (const float*)d_in[2];
    const float* W_proj = (const float*)d_in[3];
    float* out = (float*)d_out;

    const int smem_attn = 4 * 64 * 68 * (int)sizeof(float);  // 69632 B
    cudaFuncSetAttribute(attn1_kernel,
                         cudaFuncAttributeMaxDynamicSharedMemorySize, smem_attn);
    cudaFuncSetAttribute(attn2_kernel,
                         cudaFuncAttributeMaxDynamicSharedMemorySize, smem_attn);

    dim3 blk(256);
    // qk = x @ W_attn  (M=4096, N=2048, K=1024) -> g_q, g_k head layout
    sgemm_kernel<0><<<dim3(2 * TC / 128, MROWS / 128), blk>>>(
        x, W_attn, nullptr, MROWS, 2 * TC, TC);
    // k2 = x @ W_k2    (M=4096, N=1024, K=1024) -> g_k2 head layout
    sgemm_kernel<1><<<dim3(TC / 128, MROWS / 128), blk>>>(
        x, W_k2, nullptr, MROWS, TC, TC);
    // y = softmax attention
    attn1_kernel<<<dim3(TT / 64, BHN), blk, smem_attn>>>(x);
    // ysum = merge(y) + merge(y2)
    attn2_kernel<<<dim3(TT / 64, BHN), blk, smem_attn>>>(x);
    // out = ysum @ W_proj
    sgemm_kernel<2><<<dim3(TC / 128, MROWS / 128), blk>>>(
        nullptr, W_proj, out, MROWS, TC, TC);
}

// round 2
// speedup vs baseline: 1.2333x; 1.2333x over previous
#include <cuda_runtime.h>
#include <math.h>
#include <stdint.h>

#define TB 2
#define TT 2048
#define TC 1024
#define NH 16
#define HD 64
#define BHN (TB*NH)
#define MROWS (TB*TT)
#define SCALE 0.125f

// Scratch (static device allocations; allowed by harness rules)
__device__ float g_q[(size_t)BHN*TT*HD];
__device__ float g_k[(size_t)BHN*TT*HD];
__device__ float g_k2[(size_t)BHN*TT*HD];
__device__ float g_y[(size_t)BHN*TT*HD];
__device__ float g_ysum[(size_t)TB*TT*TC];

__device__ __forceinline__ uint32_t f2tf32(float f) {
    uint32_t u;
    asm volatile("cvt.rna.tf32.f32 %0, %1;" : "=r"(u) : "f"(f));
    return u;
}

__device__ __forceinline__ void mma_tf32(float c[4], const uint32_t a[4],
                                         const uint32_t b[2]) {
    asm volatile(
        "mma.sync.aligned.m16n8k8.row.col.f32.tf32.tf32.f32 "
        "{%0,%1,%2,%3}, {%4,%5,%6,%7}, {%8,%9}, {%0,%1,%2,%3};"
        : "+f"(c[0]), "+f"(c[1]), "+f"(c[2]), "+f"(c[3])
        : "r"(a[0]), "r"(a[1]), "r"(a[2]), "r"(a[3]), "r"(b[0]), "r"(b[1]));
}

// ---------------------------------------------------------------------------
// TF32 tensor-core GEMM: 128x128 block tile, BK=16, 256 threads (8 warps),
// warp tile 64x32 = 4x4 m16n8k8 mma tiles. Register-prefetch double buffer.
// MODE 0: C = x @ W_attn  -> scatter to g_q (n<C) / g_k (n>=C) head layout
// MODE 1: C = x @ W_k2    -> scatter to g_k2 head layout
// MODE 2: C = g_ysum @ W_proj -> row-major Cout
// ---------------------------------------------------------------------------
template<int MODE>
__global__ __launch_bounds__(256)
void tgemm_kernel(const float* __restrict__ A, const float* __restrict__ Bw,
                  float* __restrict__ Cout, int M, int N, int K)
{
    // pitch 136 words: fragment LDS bank = 8*(k&3) + (lane>>2) -> 32 distinct
    __shared__ uint32_t As[16][136];   // [k][m]
    __shared__ uint32_t Bs[16][136];   // [k][n]

    const int tid = threadIdx.x;
    const int lane = tid & 31;
    const int warp = tid >> 5;
    const int warpM = warp >> 2;      // 0..1  (64 rows)
    const int warpN = warp & 3;       // 0..3  (32 cols)
    const int g = lane >> 2;          // 0..7
    const int t = lane & 3;           // 0..3

    const int bm = blockIdx.y * 128;
    const int bn = blockIdx.x * 128;
    const float* Ap = (MODE == 2) ? (const float*)g_ysum : A;

    float acc[4][4][4];
#pragma unroll
    for (int i = 0; i < 4; i++)
#pragma unroll
        for (int j = 0; j < 4; j++)
#pragma unroll
            for (int r = 0; r < 4; r++) acc[i][j][r] = 0.f;

    // per-thread global load coordinates (2 float4 each for A and B per iter)
    const int aRow0 = tid >> 2,            aq0 = (tid & 3) << 2;
    const int aRow1 = (tid + 256) >> 2,    aq1 = aq0;
    const int bRow0 = tid >> 5,            bc0 = (tid & 31) << 2;
    const int bRow1 = (tid + 256) >> 5,    bc1 = bc0;

    float4 pa0, pa1, pb0, pb1;
    // prologue prefetch kt=0
    pa0 = *(const float4*)(Ap + (size_t)(bm + aRow0) * K + aq0);
    pa1 = *(const float4*)(Ap + (size_t)(bm + aRow1) * K + aq1);
    pb0 = *(const float4*)(Bw + (size_t)(bRow0) * N + bn + bc0);
    pb1 = *(const float4*)(Bw + (size_t)(bRow1) * N + bn + bc1);

    for (int kt = 0; kt < K; kt += 16) {
        __syncthreads();   // previous compute done before overwriting smem
        // store staged tile (convert fp32 -> tf32)
        As[aq0 + 0][aRow0] = f2tf32(pa0.x);
        As[aq0 + 1][aRow0] = f2tf32(pa0.y);
        As[aq0 + 2][aRow0] = f2tf32(pa0.z);
        As[aq0 + 3][aRow0] = f2tf32(pa0.w);
        As[aq1 + 0][aRow1] = f2tf32(pa1.x);
        As[aq1 + 1][aRow1] = f2tf32(pa1.y);
        As[aq1 + 2][aRow1] = f2tf32(pa1.z);
        As[aq1 + 3][aRow1] = f2tf32(pa1.w);
        Bs[bRow0][bc0 + 0] = f2tf32(pb0.x);
        Bs[bRow0][bc0 + 1] = f2tf32(pb0.y);
        Bs[bRow0][bc0 + 2] = f2tf32(pb0.z);
        Bs[bRow0][bc0 + 3] = f2tf32(pb0.w);
        Bs[bRow1][bc1 + 0] = f2tf32(pb1.x);
        Bs[bRow1][bc1 + 1] = f2tf32(pb1.y);
        Bs[bRow1][bc1 + 2] = f2tf32(pb1.z);
        Bs[bRow1][bc1 + 3] = f2tf32(pb1.w);
        __syncthreads();

        // prefetch next tile into registers (overlaps with mma compute)
        if (kt + 16 < K) {
            int kn = kt + 16;
            pa0 = *(const float4*)(Ap + (size_t)(bm + aRow0) * K + kn + aq0);
            pa1 = *(const float4*)(Ap + (size_t)(bm + aRow1) * K + kn + aq1);
            pb0 = *(const float4*)(Bw + (size_t)(kn + bRow0) * N + bn + bc0);
            pb1 = *(const float4*)(Bw + (size_t)(kn + bRow1) * N + bn + bc1);
        }

#pragma unroll
        for (int ks = 0; ks < 2; ks++) {
            const int k0 = ks * 8;
            uint32_t af[4][4], bf[4][2];
#pragma unroll
            for (int i = 0; i < 4; i++) {
                int m0 = warpM * 64 + i * 16;
                af[i][0] = As[k0 + t][m0 + g];
                af[i][1] = As[k0 + t][m0 + g + 8];
                af[i][2] = As[k0 + t + 4][m0 + g];
                af[i][3] = As[k0 + t + 4][m0 + g + 8];
            }
#pragma unroll
            for (int j = 0; j < 4; j++) {
                int n0 = warpN * 32 + j * 8;
                bf[j][0] = Bs[k0 + t][n0 + g];
                bf[j][1] = Bs[k0 + t + 4][n0 + g];
            }
#pragma unroll
            for (int i = 0; i < 4; i++)
#pragma unroll
                for (int j = 0; j < 4; j++)
                    mma_tf32(acc[i][j], af[i], bf[j]);
        }
    }

    // Epilogue: c0,c1 at (row g, cols 2t,2t+1); c2,c3 at (row g+8)
#pragma unroll
    for (int i = 0; i < 4; i++) {
#pragma unroll
        for (int j = 0; j < 4; j++) {
            int col = bn + warpN * 32 + j * 8 + t * 2;
#pragma unroll
            for (int half = 0; half < 2; half++) {
                int m = bm + warpM * 64 + i * 16 + g + half * 8;
                float2 v = half == 0 ? make_float2(acc[i][j][0], acc[i][j][1])
                                     : make_float2(acc[i][j][2], acc[i][j][3]);
                if (MODE == 2) {
                    *(float2*)(Cout + (size_t)m * N + col) = v;
                } else {
                    int b = m >> 11;            // / TT
                    int tt = m & (TT - 1);
                    float* base;
                    int nn = col;
                    if (MODE == 0) {
                        base = g_q;
                        if (nn >= TC) { nn -= TC; base = g_k; }
                    } else {
                        base = g_k2;
                    }
                    int h = nn >> 6, dd = nn & 63;
                    *(float2*)(base + (((size_t)(b * NH + h) * TT + tt) << 6) + dd) = v;
                }
            }
        }
    }
}

// ---------------------------------------------------------------------------
// Flash attention (causal softmax). 64x64 tiles, 256 threads (16x16),
// each thread 4x4 score fragment + 4x4 output slice. (unchanged this round)
// ---------------------------------------------------------------------------
__global__ __launch_bounds__(256)
void attn1_kernel(const float* __restrict__ x)
{
    extern __shared__ float sm[];
    float* Qs = sm;
    float* Ks = sm + 64 * 68;
    float* Vs = sm + 2 * 64 * 68;
    float* Ps = sm + 3 * 64 * 68;

    const int tid = threadIdx.x;
    const int bh = blockIdx.y;
    const int b = bh >> 4, h = bh & 15;
    const int q0 = blockIdx.x * 64;
    const float* qptr = g_q + (size_t)bh * TT * HD;
    const float* kptr = g_k + (size_t)bh * TT * HD;
    const float* vptr = x + (size_t)b * TT * TC + h * HD;

#pragma unroll
    for (int l = 0; l < 4; l++) {
        int idx = tid + l * 256;
        int row = idx >> 4, cq = (idx & 15) << 2;
        float4 v = *(const float4*)(qptr + (size_t)(q0 + row) * HD + cq);
        float* d = Qs + row * 68 + cq;
        d[0] = v.x * SCALE; d[1] = v.y * SCALE;
        d[2] = v.z * SCALE; d[3] = v.w * SCALE;
    }

    const int tr = tid >> 4, tc = tid & 15;
    float m_run[4], l_run[4], O[4][4];
#pragma unroll
    for (int i = 0; i < 4; i++) {
        m_run[i] = -1e30f; l_run[i] = 0.f;
#pragma unroll
        for (int j = 0; j < 4; j++) O[i][j] = 0.f;
    }

    const int ntiles = blockIdx.x + 1;
    for (int kt = 0; kt < ntiles; kt++) {
        const int s0 = kt * 64;
        __syncthreads();
#pragma unroll
        for (int l = 0; l < 4; l++) {
            int idx = tid + l * 256;
            int row = idx >> 4, cq = (idx & 15) << 2;
            *(float4*)(Ks + row * 68 + cq) =
                *(const float4*)(kptr + (size_t)(s0 + row) * HD + cq);
            *(float4*)(Vs + row * 68 + cq) =
                *(const float4*)(vptr + (size_t)(s0 + row) * TC + cq);
        }
        __syncthreads();

        float S[4][4];
#pragma unroll
        for (int i = 0; i < 4; i++)
#pragma unroll
            for (int j = 0; j < 4; j++) S[i][j] = 0.f;

#pragma unroll
        for (int d0 = 0; d0 < HD; d0 += 4) {
            float qv[4][4], kv[4][4];
#pragma unroll
            for (int i = 0; i < 4; i++) {
                float4 t4 = *(const float4*)(Qs + (tr * 4 + i) * 68 + d0);
                qv[i][0] = t4.x; qv[i][1] = t4.y; qv[i][2] = t4.z; qv[i][3] = t4.w;
            }
#pragma unroll
            for (int j = 0; j < 4; j++) {
                float4 t4 = *(const float4*)(Ks + (tc * 4 + j) * 68 + d0);
                kv[j][0] = t4.x; kv[j][1] = t4.y; kv[j][2] = t4.z; kv[j][3] = t4.w;
            }
#pragma unroll
            for (int i = 0; i < 4; i++)
#pragma unroll
                for (int j = 0; j < 4; j++)
#pragma unroll
                    for (int dd = 0; dd < 4; dd++)
                        S[i][j] += qv[i][dd] * kv[j][dd];
        }

        if (kt == blockIdx.x) {
#pragma unroll
            for (int i = 0; i < 4; i++)
#pragma unroll
                for (int j = 0; j < 4; j++)
                    if (tc * 4 + j > tr * 4 + i) S[i][j] = -1e30f;
        }

        float mt[4];
#pragma unroll
        for (int i = 0; i < 4; i++)
            mt[i] = fmaxf(fmaxf(S[i][0], S[i][1]), fmaxf(S[i][2], S[i][3]));
#pragma unroll
        for (int off = 8; off > 0; off >>= 1)
#pragma unroll
            for (int i = 0; i < 4; i++)
                mt[i] = fmaxf(mt[i], __shfl_xor_sync(0xffffffffu, mt[i], off));

        float corr[4];
#pragma unroll
        for (int i = 0; i < 4; i++) {
            float mn = fmaxf(m_run[i], mt[i]);
            corr[i] = __expf(m_run[i] - mn);
            m_run[i] = mn;
        }
        float rs[4];
#pragma unroll
        for (int i = 0; i < 4; i++) {
            float r = 0.f;
#pragma unroll
            for (int j = 0; j < 4; j++) {
                S[i][j] = __expf(S[i][j] - m_run[i]);
                r += S[i][j];
            }
            rs[i] = r;
        }
#pragma unroll
        for (int off = 8; off > 0; off >>= 1)
#pragma unroll
            for (int i = 0; i < 4; i++)
                rs[i] += __shfl_xor_sync(0xffffffffu, rs[i], off);
#pragma unroll
        for (int i = 0; i < 4; i++) {
            l_run[i] = l_run[i] * corr[i] + rs[i];
#pragma unroll
            for (int j = 0; j < 4; j++) O[i][j] *= corr[i];
        }
#pragma unroll
        for (int i = 0; i < 4; i++)
            *(float4*)(Ps + (tr * 4 + i) * 68 + tc * 4) =
                make_float4(S[i][0], S[i][1], S[i][2], S[i][3]);
        __syncthreads();

#pragma unroll
        for (int j0 = 0; j0 < 64; j0 += 4) {
            float pv[4][4];
#pragma unroll
            for (int i = 0; i < 4; i++) {
                float4 t4 = *(const float4*)(Ps + (tr * 4 + i) * 68 + j0);
                pv[i][0] = t4.x; pv[i][1] = t4.y; pv[i][2] = t4.z; pv[i][3] = t4.w;
            }
#pragma unroll
            for (int jj = 0; jj < 4; jj++) {
                float4 vv = *(const float4*)(Vs + (j0 + jj) * 68 + tc * 4);
#pragma unroll
                for (int i = 0; i < 4; i++) {
                    O[i][0] += pv[i][jj] * vv.x;
                    O[i][1] += pv[i][jj] * vv.y;
                    O[i][2] += pv[i][jj] * vv.z;
                    O[i][3] += pv[i][jj] * vv.w;
                }
            }
        }
    }

    float* ybase = g_y + (size_t)bh * TT * HD;
#pragma unroll
    for (int i = 0; i < 4; i++) {
        float inv = 1.f / l_run[i];
        *(float4*)(ybase + (size_t)(q0 + tr * 4 + i) * HD + tc * 4) =
            make_float4(O[i][0] * inv, O[i][1] * inv, O[i][2] * inv, O[i][3] * inv);
    }
}

// ---------------------------------------------------------------------------
// ARMA attention pass (unchanged this round)
// ---------------------------------------------------------------------------
__global__ __launch_bounds__(256)
void attn2_kernel(const float* __restrict__ x)
{
    extern __shared__ float sm[];
    float* Qs = sm;
    float* Ks = sm + 64 * 68;
    float* Es = sm + 2 * 64 * 68;
    float* Ps = sm + 3 * 64 * 68;

    const int tid = threadIdx.x;
    const int bh = blockIdx.y;
    const int b = bh >> 4, h = bh & 15;
    const int q0 = blockIdx.x * 64;
    const float* qptr = g_q + (size_t)bh * TT * HD;
    const float* k2ptr = g_k2 + (size_t)bh * TT * HD;
    const float* ybase = g_y + (size_t)bh * TT * HD;
    const float* vptr = x + (size_t)b * TT * TC + h * HD;

#pragma unroll
    for (int l = 0; l < 4; l++) {
        int idx = tid + l * 256;
        int row = idx >> 4, cq = (idx & 15) << 2;
        float4 v = *(const float4*)(qptr + (size_t)(q0 + row) * HD + cq);
        float* d = Qs + row * 68 + cq;
        float q0v = v.x * SCALE, q1v = v.y * SCALE, q2v = v.z * SCALE, q3v = v.w * SCALE;
        d[0] = fminf(q0v, 0.02f * q0v);
        d[1] = fminf(q1v, 0.02f * q1v);
        d[2] = fminf(q2v, 0.02f * q2v);
        d[3] = fminf(q3v, 0.02f * q3v);
    }

    const int tr = tid >> 4, tc = tid & 15;
    float O[4][4];
#pragma unroll
    for (int i = 0; i < 4; i++)
#pragma unroll
        for (int j = 0; j < 4; j++) O[i][j] = 0.f;

    const int ntiles = blockIdx.x + 1;
    for (int kt = 0; kt < ntiles; kt++) {
        const int s0 = kt * 64;
        __syncthreads();
#pragma unroll
        for (int l = 0; l < 4; l++) {
            int idx = tid + l * 256;
            int row = idx >> 4, cq = (idx & 15) << 2;
            int s = s0 + row;
            float4 kv = *(const float4*)(k2ptr + (size_t)s * HD + cq);
            float* kd = Ks + row * 68 + cq;
            kd[0] = 1.f / (1.f + __expf(-0.0025f * kv.x));
            kd[1] = 1.f / (1.f + __expf(-0.0025f * kv.y));
            kd[2] = 1.f / (1.f + __expf(-0.0025f * kv.z));
            kd[3] = 1.f / (1.f + __expf(-0.0025f * kv.w));
            float* ed = Es + row * 68 + cq;
            if (s + 1 < TT) {
                float4 xv = *(const float4*)(vptr + (size_t)(s + 1) * TC + cq);
                float4 yv = *(const float4*)(ybase + (size_t)s * HD + cq);
                ed[0] = xv.x - yv.x; ed[1] = xv.y - yv.y;
                ed[2] = xv.z - yv.z; ed[3] = xv.w - yv.w;
            } else {
                ed[0] = 0.f; ed[1] = 0.f; ed[2] = 0.f; ed[3] = 0.f;
            }
        }
        __syncthreads();

        float S[4][4];
#pragma unroll
        for (int i = 0; i < 4; i++)
#pragma unroll
            for (int j = 0; j < 4; j++) S[i][j] = 0.f;

#pragma unroll
        for (int d0 = 0; d0 < HD; d0 += 4) {
            float qv[4][4], kv[4][4];
#pragma unroll
            for (int i = 0; i < 4; i++) {
                float4 t4 = *(const float4*)(Qs + (tr * 4 + i) * 68 + d0);
                qv[i][0] = t4.x; qv[i][1] = t4.y; qv[i][2] = t4.z; qv[i][3] = t4.w;
            }
#pragma unroll
            for (int j = 0; j < 4; j++) {
                float4 t4 = *(const float4*)(Ks + (tc * 4 + j) * 68 + d0);
                kv[j][0] = t4.x; kv[j][1] = t4.y; kv[j][2] = t4.z; kv[j][3] = t4.w;
            }
#pragma unroll
            for (int i = 0; i < 4; i++)
#pragma unroll
                for (int j = 0; j < 4; j++)
#pragma unroll
                    for (int dd = 0; dd < 4; dd++)
                        S[i][j] += qv[i][dd] * kv[j][dd];
        }

        if (kt == blockIdx.x) {
#pragma unroll
            for (int i = 0; i < 4; i++)
#pragma unroll
                for (int j = 0; j < 4; j++)
                    if (!(tc * 4 + j < tr * 4 + i)) S[i][j] = 0.f;
        }

#pragma unroll
        for (int i = 0; i < 4; i++)
            *(float4*)(Ps + (tr * 4 + i) * 68 + tc * 4) =
                make_float4(S[i][0], S[i][1], S[i][2], S[i][3]);
        __syncthreads();

#pragma unroll
        for (int j0 = 0; j0 < 64; j0 += 4) {
            float pv[4][4];
#pragma unroll
            for (int i = 0; i < 4; i++) {
                float4 t4 = *(const float4*)(Ps + (tr * 4 + i) * 68 + j0);
                pv[i][0] = t4.x; pv[i][1] = t4.y; pv[i][2] = t4.z; pv[i][3] = t4.w;
            }
#pragma unroll
            for (int jj = 0; jj < 4; jj++) {
                float4 vv = *(const float4*)(Es + (j0 + jj) * 68 + tc * 4);
#pragma unroll
                for (int i = 0; i < 4; i++) {
                    O[i][0] += pv[i][jj] * vv.x;
                    O[i][1] += pv[i][jj] * vv.y;
                    O[i][2] += pv[i][jj] * vv.z;
                    O[i][3] += pv[i][jj] * vv.w;
                }
            }
        }
    }

#pragma unroll
    for (int i = 0; i < 4; i++) {
        int r = q0 + tr * 4 + i;
        float4 yv = *(const float4*)(ybase + (size_t)r * HD + tc * 4);
        *(float4*)(g_ysum + ((size_t)b * TT + r) * TC + h * HD + tc * 4) =
            make_float4(O[i][0] + yv.x, O[i][1] + yv.y,
                        O[i][2] + yv.z, O[i][3] + yv.w);
    }
}

// ---------------------------------------------------------------------------
extern "C" void kernel_launch(void* const* d_in, const int* in_sizes, int n_in,
                              void* d_out, int out_size)
{
    (void)in_sizes; (void)n_in; (void)out_size;
    const float* x      = (const float*)d_in[0];
    const float* W_attn = (const float*)d_in[1];
    const float* W_k2   = (const float*)d_in[2];
    const float* W_proj = (const float*)d_in[3];
    float* out = (float*)d_out;

    const int smem_attn = 4 * 64 * 68 * (int)sizeof(float);  // 69632 B
    cudaFuncSetAttribute(attn1_kernel,
                         cudaFuncAttributeMaxDynamicSharedMemorySize, smem_attn);
    cudaFuncSetAttribute(attn2_kernel,
                         cudaFuncAttributeMaxDynamicSharedMemorySize, smem_attn);

    dim3 blk(256);
    tgemm_kernel<0><<<dim3(2 * TC / 128, MROWS / 128), blk>>>(
        x, W_attn, nullptr, MROWS, 2 * TC, TC);
    tgemm_kernel<1><<<dim3(TC / 128, MROWS / 128), blk>>>(
        x, W_k2, nullptr, MROWS, TC, TC);
    attn1_kernel<<<dim3(TT / 64, BHN), blk, smem_attn>>>(x);
    attn2_kernel<<<dim3(TT / 64, BHN), blk, smem_attn>>>(x);
    tgemm_kernel<2><<<dim3(TC / 128, MROWS / 128), blk>>>(
        nullptr, W_proj, out, MROWS, TC, TC);
}

// round 3
// speedup vs baseline: 1.9503x; 1.5813x over previous
#include <cuda_runtime.h>
#include <math.h>
#include <stdint.h>

#define TB 2
#define TT 2048
#define TC 1024
#define NH 16
#define HD 64
#define BHN (TB*NH)
#define MROWS (TB*TT)
#define SCALE 0.125f

#define PQ 68   // pitch for Q/K/P tiles
#define PVV 72  // pitch for V/E tiles

// Scratch
__device__ float g_q[(size_t)BHN*TT*HD];
__device__ float g_k[(size_t)BHN*TT*HD];
__device__ float g_k2[(size_t)BHN*TT*HD];
__device__ float g_y[(size_t)BHN*TT*HD];
__device__ float g_ysum[(size_t)TB*TT*TC];

__device__ __forceinline__ uint32_t f2tf32(float f) {
    uint32_t u;
    asm volatile("cvt.rna.tf32.f32 %0, %1;" : "=r"(u) : "f"(f));
    return u;
}
__device__ __forceinline__ void split_tf32(float v, uint32_t& hi, uint32_t& lo) {
    hi = f2tf32(v);
    lo = f2tf32(v - __uint_as_float(hi));
}

__device__ __forceinline__ void mma_tf32(float c[4], const uint32_t a[4],
                                         const uint32_t b[2]) {
    asm volatile(
        "mma.sync.aligned.m16n8k8.row.col.f32.tf32.tf32.f32 "
        "{%0,%1,%2,%3}, {%4,%5,%6,%7}, {%8,%9}, {%0,%1,%2,%3};"
        : "+f"(c[0]), "+f"(c[1]), "+f"(c[2]), "+f"(c[3])
        : "r"(a[0]), "r"(a[1]), "r"(a[2]), "r"(a[3]), "r"(b[0]), "r"(b[1]));
}

// ---------------------------------------------------------------------------
// TF32 tensor-core GEMM (unchanged from round 2)
// ---------------------------------------------------------------------------
template<int MODE>
__global__ __launch_bounds__(256)
void tgemm_kernel(const float* __restrict__ A, const float* __restrict__ Bw,
                  float* __restrict__ Cout, int M, int N, int K)
{
    __shared__ uint32_t As[16][136];
    __shared__ uint32_t Bs[16][136];

    const int tid = threadIdx.x;
    const int lane = tid & 31;
    const int warp = tid >> 5;
    const int warpM = warp >> 2;
    const int warpN = warp & 3;
    const int g = lane >> 2;
    const int t = lane & 3;

    const int bm = blockIdx.y * 128;
    const int bn = blockIdx.x * 128;
    const float* Ap = (MODE == 2) ? (const float*)g_ysum : A;

    float acc[4][4][4];
#pragma unroll
    for (int i = 0; i < 4; i++)
#pragma unroll
        for (int j = 0; j < 4; j++)
#pragma unroll
            for (int r = 0; r < 4; r++) acc[i][j][r] = 0.f;

    const int aRow0 = tid >> 2,            aq0 = (tid & 3) << 2;
    const int aRow1 = (tid + 256) >> 2,    aq1 = aq0;
    const int bRow0 = tid >> 5,            bc0 = (tid & 31) << 2;
    const int bRow1 = (tid + 256) >> 5,    bc1 = bc0;

    float4 pa0, pa1, pb0, pb1;
    pa0 = *(const float4*)(Ap + (size_t)(bm + aRow0) * K + aq0);
    pa1 = *(const float4*)(Ap + (size_t)(bm + aRow1) * K + aq1);
    pb0 = *(const float4*)(Bw + (size_t)(bRow0) * N + bn + bc0);
    pb1 = *(const float4*)(Bw + (size_t)(bRow1) * N + bn + bc1);

    for (int kt = 0; kt < K; kt += 16) {
        __syncthreads();
        As[aq0 + 0][aRow0] = f2tf32(pa0.x);
        As[aq0 + 1][aRow0] = f2tf32(pa0.y);
        As[aq0 + 2][aRow0] = f2tf32(pa0.z);
        As[aq0 + 3][aRow0] = f2tf32(pa0.w);
        As[aq1 + 0][aRow1] = f2tf32(pa1.x);
        As[aq1 + 1][aRow1] = f2tf32(pa1.y);
        As[aq1 + 2][aRow1] = f2tf32(pa1.z);
        As[aq1 + 3][aRow1] = f2tf32(pa1.w);
        Bs[bRow0][bc0 + 0] = f2tf32(pb0.x);
        Bs[bRow0][bc0 + 1] = f2tf32(pb0.y);
        Bs[bRow0][bc0 + 2] = f2tf32(pb0.z);
        Bs[bRow0][bc0 + 3] = f2tf32(pb0.w);
        Bs[bRow1][bc1 + 0] = f2tf32(pb1.x);
        Bs[bRow1][bc1 + 1] = f2tf32(pb1.y);
        Bs[bRow1][bc1 + 2] = f2tf32(pb1.z);
        Bs[bRow1][bc1 + 3] = f2tf32(pb1.w);
        __syncthreads();

        if (kt + 16 < K) {
            int kn = kt + 16;
            pa0 = *(const float4*)(Ap + (size_t)(bm + aRow0) * K + kn + aq0);
            pa1 = *(const float4*)(Ap + (size_t)(bm + aRow1) * K + kn + aq1);
            pb0 = *(const float4*)(Bw + (size_t)(kn + bRow0) * N + bn + bc0);
            pb1 = *(const float4*)(Bw + (size_t)(kn + bRow1) * N + bn + bc1);
        }

#pragma unroll
        for (int ks = 0; ks < 2; ks++) {
            const int k0 = ks * 8;
            uint32_t af[4][4], bf[4][2];
#pragma unroll
            for (int i = 0; i < 4; i++) {
                int m0 = warpM * 64 + i * 16;
                af[i][0] = As[k0 + t][m0 + g];
                af[i][1] = As[k0 + t][m0 + g + 8];
                af[i][2] = As[k0 + t + 4][m0 + g];
                af[i][3] = As[k0 + t + 4][m0 + g + 8];
            }
#pragma unroll
            for (int j = 0; j < 4; j++) {
                int n0 = warpN * 32 + j * 8;
                bf[j][0] = Bs[k0 + t][n0 + g];
                bf[j][1] = Bs[k0 + t + 4][n0 + g];
            }
#pragma unroll
            for (int i = 0; i < 4; i++)
#pragma unroll
                for (int j = 0; j < 4; j++)
                    mma_tf32(acc[i][j], af[i], bf[j]);
        }
    }

#pragma unroll
    for (int i = 0; i < 4; i++) {
#pragma unroll
        for (int j = 0; j < 4; j++) {
            int col = bn + warpN * 32 + j * 8 + t * 2;
#pragma unroll
            for (int half = 0; half < 2; half++) {
                int m = bm + warpM * 64 + i * 16 + g + half * 8;
                float2 v = half == 0 ? make_float2(acc[i][j][0], acc[i][j][1])
                                     : make_float2(acc[i][j][2], acc[i][j][3]);
                if (MODE == 2) {
                    *(float2*)(Cout + (size_t)m * N + col) = v;
                } else {
                    int b = m >> 11;
                    int tt = m & (TT - 1);
                    float* base;
                    int nn = col;
                    if (MODE == 0) {
                        base = g_q;
                        if (nn >= TC) { nn -= TC; base = g_k; }
                    } else {
                        base = g_k2;
                    }
                    int h = nn >> 6, dd = nn & 63;
                    *(float2*)(base + (((size_t)(b * NH + h) * TT + tt) << 6) + dd) = v;
                }
            }
        }
    }
}

// ---------------------------------------------------------------------------
// Fused tensor-core attention. ARMA=0: causal softmax attention -> g_y.
// ARMA=1: strict-lower w@e pass, writes g_ysum = y + y2.
// 128 threads (4 warps), Br=Bc=64. Warp w owns q-rows [w*16, w*16+16).
// S via 3xTF32 (hi/lo error compensation), PV via 2xTF32 (P exact, V hi).
// smem: Qhi,Qlo [64][68]; KP hi,lo [64][68] (K tile, reused for P);
//       Vh [64][72]. Total 88064 B -> 2 CTAs/SM.
// ---------------------------------------------------------------------------
template<int ARMA>
__global__ __launch_bounds__(128)
void fattn_kernel(const float* __restrict__ x)
{
    extern __shared__ float sm[];
    float* Qh  = sm;                  // [64][PQ]
    float* Ql  = Qh + 64 * PQ;
    float* KPh = Ql + 64 * PQ;        // K tile hi, later P hi
    float* KPl = KPh + 64 * PQ;
    float* Vh  = KPl + 64 * PQ;       // [64][PVV]

    const int tid = threadIdx.x;
    const int lane = tid & 31;
    const int warp = tid >> 5;
    const int g = lane >> 2;
    const int t = lane & 3;

    const int bh = blockIdx.y;
    const int b = bh >> 4, h = bh & 15;
    const int qb = (int)gridDim.x - 1 - (int)blockIdx.x;  // heavy blocks first
    const int q0 = qb * 64;

    const float* qptr = g_q + (size_t)bh * TT * HD;
    const float* kptr = (ARMA ? g_k2 : g_k) + (size_t)bh * TT * HD;
    const float* vx   = x + (size_t)b * TT * TC + h * HD;    // row stride TC
    const float* yb   = g_y + (size_t)bh * TT * HD;

    // ---- load Q tile (pre-scaled; ARMA applies qa transform), split hi/lo
    const int lr = tid >> 4;          // 0..7
    const int lc4 = (tid & 15) << 2;  // 0..60
#pragma unroll
    for (int it = 0; it < 8; it++) {
        int r = lr + it * 8;
        float4 v = *(const float4*)(qptr + (size_t)(q0 + r) * HD + lc4);
        float f[4] = {v.x * SCALE, v.y * SCALE, v.z * SCALE, v.w * SCALE};
        if (ARMA) {
#pragma unroll
            for (int i = 0; i < 4; i++) f[i] = fminf(f[i], 0.02f * f[i]);
        }
        uint32_t hi[4], lo[4];
#pragma unroll
        for (int i = 0; i < 4; i++) split_tf32(f[i], hi[i], lo[i]);
        *(uint4*)(Qh + r * PQ + lc4) = make_uint4(hi[0], hi[1], hi[2], hi[3]);
        *(uint4*)(Ql + r * PQ + lc4) = make_uint4(lo[0], lo[1], lo[2], lo[3]);
    }

    float O[8][4];
#pragma unroll
    for (int n = 0; n < 8; n++)
#pragma unroll
        for (int c = 0; c < 4; c++) O[n][c] = 0.f;
    float m_run[2] = {-1e30f, -1e30f};
    float l_run[2] = {0.f, 0.f};

    const int qrow0 = q0 + warp * 16 + g;       // global q row for c0,c1
    const int qrow1 = qrow0 + 8;                // for c2,c3

    for (int kt = 0; kt <= qb; kt++) {
        const int s0 = kt * 64;
        __syncthreads();   // previous PV done before overwriting KP/V

        // ---- stage K (hi/lo) and V/E (hi) tiles
#pragma unroll
        for (int it = 0; it < 8; it++) {
            int r = lr + it * 8;
            int s = s0 + r;
            float4 kv = *(const float4*)(kptr + (size_t)s * HD + lc4);
            float f[4] = {kv.x, kv.y, kv.z, kv.w};
            if (ARMA) {
#pragma unroll
                for (int i = 0; i < 4; i++)
                    f[i] = 1.f / (1.f + __expf(-0.0025f * f[i]));
            }
            uint32_t hi[4], lo[4];
#pragma unroll
            for (int i = 0; i < 4; i++) split_tf32(f[i], hi[i], lo[i]);
            *(uint4*)(KPh + r * PQ + lc4) = make_uint4(hi[0], hi[1], hi[2], hi[3]);
            *(uint4*)(KPl + r * PQ + lc4) = make_uint4(lo[0], lo[1], lo[2], lo[3]);

            float e[4];
            if (ARMA) {
                if (s + 1 < TT) {
                    float4 xv = *(const float4*)(vx + (size_t)(s + 1) * TC + lc4);
                    float4 yv = *(const float4*)(yb + (size_t)s * HD + lc4);
                    e[0] = xv.x - yv.x; e[1] = xv.y - yv.y;
                    e[2] = xv.z - yv.z; e[3] = xv.w - yv.w;
                } else {
                    e[0] = e[1] = e[2] = e[3] = 0.f;
                }
            } else {
                float4 vv = *(const float4*)(vx + (size_t)s * TC + lc4);
                e[0] = vv.x; e[1] = vv.y; e[2] = vv.z; e[3] = vv.w;
            }
            *(uint4*)(Vh + r * PVV + lc4) =
                make_uint4(f2tf32(e[0]), f2tf32(e[1]), f2tf32(e[2]), f2tf32(e[3]));
        }
        __syncthreads();

        // ---- S = Q @ K^T  (3xTF32)
        float acc[8][4];
#pragma unroll
        for (int n = 0; n < 8; n++)
#pragma unroll
            for (int c = 0; c < 4; c++) acc[n][c] = 0.f;

        const uint32_t* Qhu = (const uint32_t*)Qh;
        const uint32_t* Qlu = (const uint32_t*)Ql;
        const uint32_t* Khu = (const uint32_t*)KPh;
        const uint32_t* Klu = (const uint32_t*)KPl;
        const uint32_t* Vhu = (const uint32_t*)Vh;

#pragma unroll
        for (int k0 = 0; k0 < 64; k0 += 8) {
            uint32_t ah[4], al[4];
            int mr = warp * 16 + g;
            ah[0] = Qhu[mr * PQ + k0 + t];
            ah[1] = Qhu[(mr + 8) * PQ + k0 + t];
            ah[2] = Qhu[mr * PQ + k0 + t + 4];
            ah[3] = Qhu[(mr + 8) * PQ + k0 + t + 4];
            al[0] = Qlu[mr * PQ + k0 + t];
            al[1] = Qlu[(mr + 8) * PQ + k0 + t];
            al[2] = Qlu[mr * PQ + k0 + t + 4];
            al[3] = Qlu[(mr + 8) * PQ + k0 + t + 4];
#pragma unroll
            for (int n = 0; n < 8; n++) {
                uint32_t bh2[2], bl2[2];
                int sr = n * 8 + g;
                bh2[0] = Khu[sr * PQ + k0 + t];
                bh2[1] = Khu[sr * PQ + k0 + t + 4];
                bl2[0] = Klu[sr * PQ + k0 + t];
                bl2[1] = Klu[sr * PQ + k0 + t + 4];
                mma_tf32(acc[n], ah, bh2);
                mma_tf32(acc[n], al, bh2);
                mma_tf32(acc[n], ah, bl2);
            }
        }

        // ---- mask (diagonal tile only)
        if (kt == qb) {
#pragma unroll
            for (int n = 0; n < 8; n++) {
                int col = s0 + n * 8 + 2 * t;
#pragma unroll
                for (int c = 0; c < 4; c++) {
                    int cc = col + (c & 1);
                    int rr = (c >= 2) ? qrow1 : qrow0;
                    if (ARMA) { if (cc >= rr) acc[n][c] = 0.f; }
                    else      { if (cc >  rr) acc[n][c] = -1e30f; }
                }
            }
        }

        if (!ARMA) {
            // ---- online softmax
            float mt0 = -1e30f, mt1 = -1e30f;
#pragma unroll
            for (int n = 0; n < 8; n++) {
                mt0 = fmaxf(mt0, fmaxf(acc[n][0], acc[n][1]));
                mt1 = fmaxf(mt1, fmaxf(acc[n][2], acc[n][3]));
            }
#pragma unroll
            for (int off = 1; off <= 2; off <<= 1) {
                mt0 = fmaxf(mt0, __shfl_xor_sync(0xffffffffu, mt0, off));
                mt1 = fmaxf(mt1, __shfl_xor_sync(0xffffffffu, mt1, off));
            }
            float mn0 = fmaxf(m_run[0], mt0);
            float mn1 = fmaxf(m_run[1], mt1);
            float corr0 = __expf(m_run[0] - mn0);
            float corr1 = __expf(m_run[1] - mn1);
            m_run[0] = mn0; m_run[1] = mn1;

            float ls0 = 0.f, ls1 = 0.f;
#pragma unroll
            for (int n = 0; n < 8; n++) {
                acc[n][0] = __expf(acc[n][0] - mn0);
                acc[n][1] = __expf(acc[n][1] - mn0);
                acc[n][2] = __expf(acc[n][2] - mn1);
                acc[n][3] = __expf(acc[n][3] - mn1);
                ls0 += acc[n][0] + acc[n][1];
                ls1 += acc[n][2] + acc[n][3];
            }
#pragma unroll
            for (int off = 1; off <= 2; off <<= 1) {
                ls0 += __shfl_xor_sync(0xffffffffu, ls0, off);
                ls1 += __shfl_xor_sync(0xffffffffu, ls1, off);
            }
            l_run[0] = l_run[0] * corr0 + ls0;
            l_run[1] = l_run[1] * corr1 + ls1;
#pragma unroll
            for (int n = 0; n < 8; n++) {
                O[n][0] *= corr0; O[n][1] *= corr0;
                O[n][2] *= corr1; O[n][3] *= corr1;
            }
        }

        // ---- store P (hi/lo) into KP buffers (all warps done reading K)
        __syncthreads();
        {
            uint32_t* Phu = (uint32_t*)KPh;
            uint32_t* Plu = (uint32_t*)KPl;
            int mr = warp * 16 + g;
#pragma unroll
            for (int n = 0; n < 8; n++) {
                int col = n * 8 + 2 * t;
                uint32_t h0, l0, h1, l1;
                split_tf32(acc[n][0], h0, l0);
                split_tf32(acc[n][1], h1, l1);
                *(uint2*)(Phu + mr * PQ + col) = make_uint2(h0, h1);
                *(uint2*)(Plu + mr * PQ + col) = make_uint2(l0, l1);
                split_tf32(acc[n][2], h0, l0);
                split_tf32(acc[n][3], h1, l1);
                *(uint2*)(Phu + (mr + 8) * PQ + col) = make_uint2(h0, h1);
                *(uint2*)(Plu + (mr + 8) * PQ + col) = make_uint2(l0, l1);
            }
        }
        __syncwarp();

        // ---- O += P @ V  (2xTF32: P exact, V hi)
        const uint32_t* Phu = (const uint32_t*)KPh;
        const uint32_t* Plu = (const uint32_t*)KPl;
#pragma unroll
        for (int k0 = 0; k0 < 64; k0 += 8) {
            uint32_t ah[4], al[4];
            int mr = warp * 16 + g;
            ah[0] = Phu[mr * PQ + k0 + t];
            ah[1] = Phu[(mr + 8) * PQ + k0 + t];
            ah[2] = Phu[mr * PQ + k0 + t + 4];
            ah[3] = Phu[(mr + 8) * PQ + k0 + t + 4];
            al[0] = Plu[mr * PQ + k0 + t];
            al[1] = Plu[(mr + 8) * PQ + k0 + t];
            al[2] = Plu[mr * PQ + k0 + t + 4];
            al[3] = Plu[(mr + 8) * PQ + k0 + t + 4];
#pragma unroll
            for (int n = 0; n < 8; n++) {
                uint32_t bv[2];
                bv[0] = Vhu[(k0 + t) * PVV + n * 8 + g];
                bv[1] = Vhu[(k0 + t + 4) * PVV + n * 8 + g];
                mma_tf32(O[n], ah, bv);
                mma_tf32(O[n], al, bv);
            }
        }
    }

    // ---- epilogue
    if (!ARMA) {
        float inv0 = 1.f / l_run[0];
        float inv1 = 1.f / l_run[1];
        float* yo = g_y + (size_t)bh * TT * HD;
#pragma unroll
        for (int n = 0; n < 8; n++) {
            int col = n * 8 + 2 * t;
            *(float2*)(yo + (size_t)qrow0 * HD + col) =
                make_float2(O[n][0] * inv0, O[n][1] * inv0);
            *(float2*)(yo + (size_t)qrow1 * HD + col) =
                make_float2(O[n][2] * inv1, O[n][3] * inv1);
        }
    } else {
        float* yo = g_ysum + (size_t)b * TT * TC + h * HD;
#pragma unroll
        for (int n = 0; n < 8; n++) {
            int col = n * 8 + 2 * t;
            float2 y0 = *(const float2*)(yb + (size_t)qrow0 * HD + col);
            float2 y1 = *(const float2*)(yb + (size_t)qrow1 * HD + col);
            *(float2*)(yo + (size_t)qrow0 * TC + col) =
                make_float2(O[n][0] + y0.x, O[n][1] + y0.y);
            *(float2*)(yo + (size_t)qrow1 * TC + col) =
                make_float2(O[n][2] + y1.x, O[n][3] + y1.y);
        }
    }
}

// ---------------------------------------------------------------------------
extern "C" void kernel_launch(void* const* d_in, const int* in_sizes, int n_in,
                              void* d_out, int out_size)
{
    (void)in_sizes; (void)n_in; (void)out_size;
    const float* x      = (const float*)d_in[0];
    const float* W_attn = (const float*)d_in[1];
    const float* W_k2   = (const float*)d_in[2];
    const float* W_proj = (const float*)d_in[3];
    float* out = (float*)d_out;

    const int smem_attn = (4 * 64 * PQ + 64 * PVV) * (int)sizeof(float); // 88064
    cudaFuncSetAttribute(fattn_kernel<0>,
                         cudaFuncAttributeMaxDynamicSharedMemorySize, smem_attn);
    cudaFuncSetAttribute(fattn_kernel<1>,
                         cudaFuncAttributeMaxDynamicSharedMemorySize, smem_attn);

    dim3 blk(256);
    tgemm_kernel<0><<<dim3(2 * TC / 128, MROWS / 128), blk>>>(
        x, W_attn, nullptr, MROWS, 2 * TC, TC);
    tgemm_kernel<1><<<dim3(TC / 128, MROWS / 128), blk>>>(
        x, W_k2, nullptr, MROWS, TC, TC);
    fattn_kernel<0><<<dim3(TT / 64, BHN), 128, smem_attn>>>(x);
    fattn_kernel<1><<<dim3(TT / 64, BHN), 128, smem_attn>>>(x);
    tgemm_kernel<2><<<dim3(TC / 128, MROWS / 128), blk>>>(
        nullptr, W_proj, out, MROWS, TC, TC);
}

// round 4
// speedup vs baseline: 2.4971x; 1.2804x over previous
#include <cuda_runtime.h>
#include <math.h>
#include <stdint.h>

#define TB 2
#define TT 2048
#define TC 1024
#define NH 16
#define HD 64
#define BHN (TB*NH)
#define MROWS (TB*TT)
#define SCALE 0.125f

#define PQ 68   // pitch for Q/K tiles
#define PVV 72  // pitch for V/E tiles

// Scratch
__device__ float g_q[(size_t)BHN*TT*HD];
__device__ float g_k[(size_t)BHN*TT*HD];
__device__ float g_k2[(size_t)BHN*TT*HD];
__device__ float g_y[(size_t)BHN*TT*HD];
__device__ float g_ysum[(size_t)TB*TT*TC];

__device__ __forceinline__ uint32_t f2tf32(float f) {
    uint32_t u;
    asm volatile("cvt.rna.tf32.f32 %0, %1;" : "=r"(u) : "f"(f));
    return u;
}
__device__ __forceinline__ void split_tf32(float v, uint32_t& hi, uint32_t& lo) {
    hi = f2tf32(v);
    lo = f2tf32(v - __uint_as_float(hi));
}

__device__ __forceinline__ void mma_tf32(float c[4], const uint32_t a[4],
                                         const uint32_t b[2]) {
    asm volatile(
        "mma.sync.aligned.m16n8k8.row.col.f32.tf32.tf32.f32 "
        "{%0,%1,%2,%3}, {%4,%5,%6,%7}, {%8,%9}, {%0,%1,%2,%3};"
        : "+f"(c[0]), "+f"(c[1]), "+f"(c[2]), "+f"(c[3])
        : "r"(a[0]), "r"(a[1]), "r"(a[2]), "r"(a[3]), "r"(b[0]), "r"(b[1]));
}

// ---------------------------------------------------------------------------
// TF32 tensor-core GEMM (unchanged)
// ---------------------------------------------------------------------------
template<int MODE>
__global__ __launch_bounds__(256)
void tgemm_kernel(const float* __restrict__ A, const float* __restrict__ Bw,
                  float* __restrict__ Cout, int M, int N, int K)
{
    __shared__ uint32_t As[16][136];
    __shared__ uint32_t Bs[16][136];

    const int tid = threadIdx.x;
    const int lane = tid & 31;
    const int warp = tid >> 5;
    const int warpM = warp >> 2;
    const int warpN = warp & 3;
    const int g = lane >> 2;
    const int t = lane & 3;

    const int bm = blockIdx.y * 128;
    const int bn = blockIdx.x * 128;
    const float* Ap = (MODE == 2) ? (const float*)g_ysum : A;

    float acc[4][4][4];
#pragma unroll
    for (int i = 0; i < 4; i++)
#pragma unroll
        for (int j = 0; j < 4; j++)
#pragma unroll
            for (int r = 0; r < 4; r++) acc[i][j][r] = 0.f;

    const int aRow0 = tid >> 2,            aq0 = (tid & 3) << 2;
    const int aRow1 = (tid + 256) >> 2,    aq1 = aq0;
    const int bRow0 = tid >> 5,            bc0 = (tid & 31) << 2;
    const int bRow1 = (tid + 256) >> 5,    bc1 = bc0;

    float4 pa0, pa1, pb0, pb1;
    pa0 = *(const float4*)(Ap + (size_t)(bm + aRow0) * K + aq0);
    pa1 = *(const float4*)(Ap + (size_t)(bm + aRow1) * K + aq1);
    pb0 = *(const float4*)(Bw + (size_t)(bRow0) * N + bn + bc0);
    pb1 = *(const float4*)(Bw + (size_t)(bRow1) * N + bn + bc1);

    for (int kt = 0; kt < K; kt += 16) {
        __syncthreads();
        As[aq0 + 0][aRow0] = f2tf32(pa0.x);
        As[aq0 + 1][aRow0] = f2tf32(pa0.y);
        As[aq0 + 2][aRow0] = f2tf32(pa0.z);
        As[aq0 + 3][aRow0] = f2tf32(pa0.w);
        As[aq1 + 0][aRow1] = f2tf32(pa1.x);
        As[aq1 + 1][aRow1] = f2tf32(pa1.y);
        As[aq1 + 2][aRow1] = f2tf32(pa1.z);
        As[aq1 + 3][aRow1] = f2tf32(pa1.w);
        Bs[bRow0][bc0 + 0] = f2tf32(pb0.x);
        Bs[bRow0][bc0 + 1] = f2tf32(pb0.y);
        Bs[bRow0][bc0 + 2] = f2tf32(pb0.z);
        Bs[bRow0][bc0 + 3] = f2tf32(pb0.w);
        Bs[bRow1][bc1 + 0] = f2tf32(pb1.x);
        Bs[bRow1][bc1 + 1] = f2tf32(pb1.y);
        Bs[bRow1][bc1 + 2] = f2tf32(pb1.z);
        Bs[bRow1][bc1 + 3] = f2tf32(pb1.w);
        __syncthreads();

        if (kt + 16 < K) {
            int kn = kt + 16;
            pa0 = *(const float4*)(Ap + (size_t)(bm + aRow0) * K + kn + aq0);
            pa1 = *(const float4*)(Ap + (size_t)(bm + aRow1) * K + kn + aq1);
            pb0 = *(const float4*)(Bw + (size_t)(kn + bRow0) * N + bn + bc0);
            pb1 = *(const float4*)(Bw + (size_t)(kn + bRow1) * N + bn + bc1);
        }

#pragma unroll
        for (int ks = 0; ks < 2; ks++) {
            const int k0 = ks * 8;
            uint32_t af[4][4], bf[4][2];
#pragma unroll
            for (int i = 0; i < 4; i++) {
                int m0 = warpM * 64 + i * 16;
                af[i][0] = As[k0 + t][m0 + g];
                af[i][1] = As[k0 + t][m0 + g + 8];
                af[i][2] = As[k0 + t + 4][m0 + g];
                af[i][3] = As[k0 + t + 4][m0 + g + 8];
            }
#pragma unroll
            for (int j = 0; j < 4; j++) {
                int n0 = warpN * 32 + j * 8;
                bf[j][0] = Bs[k0 + t][n0 + g];
                bf[j][1] = Bs[k0 + t + 4][n0 + g];
            }
#pragma unroll
            for (int i = 0; i < 4; i++)
#pragma unroll
                for (int j = 0; j < 4; j++)
                    mma_tf32(acc[i][j], af[i], bf[j]);
        }
    }

#pragma unroll
    for (int i = 0; i < 4; i++) {
#pragma unroll
        for (int j = 0; j < 4; j++) {
            int col = bn + warpN * 32 + j * 8 + t * 2;
#pragma unroll
            for (int half = 0; half < 2; half++) {
                int m = bm + warpM * 64 + i * 16 + g + half * 8;
                float2 v = half == 0 ? make_float2(acc[i][j][0], acc[i][j][1])
                                     : make_float2(acc[i][j][2], acc[i][j][3]);
                if (MODE == 2) {
                    *(float2*)(Cout + (size_t)m * N + col) = v;
                } else {
                    int b = m >> 11;
                    int tt = m & (TT - 1);
                    float* base;
                    int nn = col;
                    if (MODE == 0) {
                        base = g_q;
                        if (nn >= TC) { nn -= TC; base = g_k; }
                    } else {
                        base = g_k2;
                    }
                    int h = nn >> 6, dd = nn & 63;
                    *(float2*)(base + (((size_t)(b * NH + h) * TT + tt) << 6) + dd) = v;
                }
            }
        }
    }
}

// ---------------------------------------------------------------------------
// Fused tensor-core attention, 256 threads (8 warps), 64x64 tiles.
// Warp (wm = warp>>1, wn = warp&1): q-rows [wm*16,+16), s-cols [wn*32,+32).
// Each warp runs warp-local online softmax over its s-half; halves merged
// once at the end via smem. P stays in registers (shfl acc->A-frag), so the
// main loop has only the 2 staging syncs per tile.
// ---------------------------------------------------------------------------
template<int ARMA>
__global__ __launch_bounds__(256)
void fattn_kernel(const float* __restrict__ x)
{
    extern __shared__ float sm[];
    float* Qh = sm;                   // [64][PQ]
    float* Ql = Qh + 64 * PQ;
    float* Kh = Ql + 64 * PQ;
    float* Kl = Kh + 64 * PQ;
    float* Vh = Kl + 64 * PQ;         // [64][PVV]

    const int tid = threadIdx.x;
    const int lane = tid & 31;
    const int warp = tid >> 5;        // 0..7
    const int wm = warp >> 1;         // 0..3
    const int wn = warp & 1;          // 0..1
    const int g = lane >> 2;
    const int t = lane & 3;

    const int bh = blockIdx.y;
    const int b = bh >> 4, h = bh & 15;
    const int qb = (int)gridDim.x - 1 - (int)blockIdx.x;  // heavy first
    const int q0 = qb * 64;

    const float* qptr = g_q + (size_t)bh * TT * HD;
    const float* kptr = (ARMA ? g_k2 : g_k) + (size_t)bh * TT * HD;
    const float* vx   = x + (size_t)b * TT * TC + h * HD;
    const float* yb   = g_y + (size_t)bh * TT * HD;

    const int lr = tid >> 4;          // 0..15
    const int lc4 = (tid & 15) << 2;

    // ---- load Q tile (pre-scaled; ARMA: qa transform), split hi/lo
#pragma unroll
    for (int it = 0; it < 4; it++) {
        int r = lr + it * 16;
        float4 v = *(const float4*)(qptr + (size_t)(q0 + r) * HD + lc4);
        float f[4] = {v.x * SCALE, v.y * SCALE, v.z * SCALE, v.w * SCALE};
        if (ARMA) {
#pragma unroll
            for (int i = 0; i < 4; i++) f[i] = fminf(f[i], 0.02f * f[i]);
        }
        uint32_t hi[4], lo[4];
#pragma unroll
        for (int i = 0; i < 4; i++) split_tf32(f[i], hi[i], lo[i]);
        *(uint4*)(Qh + r * PQ + lc4) = make_uint4(hi[0], hi[1], hi[2], hi[3]);
        *(uint4*)(Ql + r * PQ + lc4) = make_uint4(lo[0], lo[1], lo[2], lo[3]);
    }

    float O[8][4];
#pragma unroll
    for (int n = 0; n < 8; n++)
#pragma unroll
        for (int c = 0; c < 4; c++) O[n][c] = 0.f;
    float m_run[2] = {-1e30f, -1e30f};
    float l_run[2] = {0.f, 0.f};

    const int qrow0 = q0 + wm * 16 + g;
    const int qrow1 = qrow0 + 8;
    const int sw = wn * 32;           // warp's s-col offset within tile
    const int mr = wm * 16 + g;

    const uint32_t* Qhu = (const uint32_t*)Qh;
    const uint32_t* Qlu = (const uint32_t*)Ql;
    const uint32_t* Khu = (const uint32_t*)Kh;
    const uint32_t* Klu = (const uint32_t*)Kl;
    const uint32_t* Vhu = (const uint32_t*)Vh;

    for (int kt = 0; kt <= qb; kt++) {
        const int s0 = kt * 64;
        __syncthreads();   // everyone done reading previous K/V

        // ---- stage K (hi/lo) and V/E (hi)
#pragma unroll
        for (int it = 0; it < 4; it++) {
            int r = lr + it * 16;
            int s = s0 + r;
            float4 kv = *(const float4*)(kptr + (size_t)s * HD + lc4);
            float f[4] = {kv.x, kv.y, kv.z, kv.w};
            if (ARMA) {
#pragma unroll
                for (int i = 0; i < 4; i++)
                    f[i] = 1.f / (1.f + __expf(-0.0025f * f[i]));
            }
            uint32_t hi[4], lo[4];
#pragma unroll
            for (int i = 0; i < 4; i++) split_tf32(f[i], hi[i], lo[i]);
            *(uint4*)(Kh + r * PQ + lc4) = make_uint4(hi[0], hi[1], hi[2], hi[3]);
            *(uint4*)(Kl + r * PQ + lc4) = make_uint4(lo[0], lo[1], lo[2], lo[3]);

            float e[4];
            if (ARMA) {
                if (s + 1 < TT) {
                    float4 xv = *(const float4*)(vx + (size_t)(s + 1) * TC + lc4);
                    float4 yv = *(const float4*)(yb + (size_t)s * HD + lc4);
                    e[0] = xv.x - yv.x; e[1] = xv.y - yv.y;
                    e[2] = xv.z - yv.z; e[3] = xv.w - yv.w;
                } else {
                    e[0] = e[1] = e[2] = e[3] = 0.f;
                }
            } else {
                float4 vv = *(const float4*)(vx + (size_t)s * TC + lc4);
                e[0] = vv.x; e[1] = vv.y; e[2] = vv.z; e[3] = vv.w;
            }
            *(uint4*)(Vh + r * PVV + lc4) =
                make_uint4(f2tf32(e[0]), f2tf32(e[1]), f2tf32(e[2]), f2tf32(e[3]));
        }
        __syncthreads();

        // ---- S = Q @ K^T over this warp's 32 s-cols (3xTF32)
        float acc[4][4];
#pragma unroll
        for (int nb = 0; nb < 4; nb++)
#pragma unroll
            for (int c = 0; c < 4; c++) acc[nb][c] = 0.f;

#pragma unroll
        for (int k0 = 0; k0 < 64; k0 += 8) {
            uint32_t ah[4], al[4];
            ah[0] = Qhu[mr * PQ + k0 + t];
            ah[1] = Qhu[(mr + 8) * PQ + k0 + t];
            ah[2] = Qhu[mr * PQ + k0 + t + 4];
            ah[3] = Qhu[(mr + 8) * PQ + k0 + t + 4];
            al[0] = Qlu[mr * PQ + k0 + t];
            al[1] = Qlu[(mr + 8) * PQ + k0 + t];
            al[2] = Qlu[mr * PQ + k0 + t + 4];
            al[3] = Qlu[(mr + 8) * PQ + k0 + t + 4];
#pragma unroll
            for (int nb = 0; nb < 4; nb++) {
                int sr = sw + nb * 8 + g;
                uint32_t bh2[2], bl2[2];
                bh2[0] = Khu[sr * PQ + k0 + t];
                bh2[1] = Khu[sr * PQ + k0 + t + 4];
                bl2[0] = Klu[sr * PQ + k0 + t];
                bl2[1] = Klu[sr * PQ + k0 + t + 4];
                mma_tf32(acc[nb], ah, bh2);
                mma_tf32(acc[nb], al, bh2);
                mma_tf32(acc[nb], ah, bl2);
            }
        }

        const bool diag = (kt == qb);
        if (diag) {
#pragma unroll
            for (int nb = 0; nb < 4; nb++) {
                int colb = s0 + sw + nb * 8 + 2 * t;
#pragma unroll
                for (int c = 0; c < 4; c++) {
                    int cc = colb + (c & 1);
                    int rr = (c >= 2) ? qrow1 : qrow0;
                    if (ARMA) { if (cc >= rr) acc[nb][c] = 0.f; }
                    else      { if (cc >  rr) acc[nb][c] = -1e30f; }
                }
            }
        }

        if (!ARMA) {
            // ---- warp-local online softmax (over this warp's 32 cols)
            float mt0 = -1e30f, mt1 = -1e30f;
#pragma unroll
            for (int nb = 0; nb < 4; nb++) {
                mt0 = fmaxf(mt0, fmaxf(acc[nb][0], acc[nb][1]));
                mt1 = fmaxf(mt1, fmaxf(acc[nb][2], acc[nb][3]));
            }
#pragma unroll
            for (int off = 1; off <= 2; off <<= 1) {
                mt0 = fmaxf(mt0, __shfl_xor_sync(0xffffffffu, mt0, off));
                mt1 = fmaxf(mt1, __shfl_xor_sync(0xffffffffu, mt1, off));
            }
            float mn0 = fmaxf(m_run[0], mt0);
            float mn1 = fmaxf(m_run[1], mt1);
            float corr0 = __expf(m_run[0] - mn0);
            float corr1 = __expf(m_run[1] - mn1);
            m_run[0] = mn0; m_run[1] = mn1;

            float ls0 = 0.f, ls1 = 0.f;
#pragma unroll
            for (int nb = 0; nb < 4; nb++) {
                float p0 = __expf(acc[nb][0] - mn0);
                float p1 = __expf(acc[nb][1] - mn0);
                float p2 = __expf(acc[nb][2] - mn1);
                float p3 = __expf(acc[nb][3] - mn1);
                if (diag) {  // zero masked entries (handles all-masked rows)
                    int colb = s0 + sw + nb * 8 + 2 * t;
                    if (colb     > qrow0) p0 = 0.f;
                    if (colb + 1 > qrow0) p1 = 0.f;
                    if (colb     > qrow1) p2 = 0.f;
                    if (colb + 1 > qrow1) p3 = 0.f;
                }
                acc[nb][0] = p0; acc[nb][1] = p1;
                acc[nb][2] = p2; acc[nb][3] = p3;
                ls0 += p0 + p1;
                ls1 += p2 + p3;
            }
#pragma unroll
            for (int off = 1; off <= 2; off <<= 1) {
                ls0 += __shfl_xor_sync(0xffffffffu, ls0, off);
                ls1 += __shfl_xor_sync(0xffffffffu, ls1, off);
            }
            l_run[0] = l_run[0] * corr0 + ls0;
            l_run[1] = l_run[1] * corr1 + ls1;
#pragma unroll
            for (int n = 0; n < 8; n++) {
                O[n][0] *= corr0; O[n][1] *= corr0;
                O[n][2] *= corr1; O[n][3] *= corr1;
            }
        }

        // ---- O += P @ V : P from registers via shfl (no smem, no syncs)
#pragma unroll
        for (int nb = 0; nb < 4; nb++) {
            int src0 = (lane & ~3) | (t >> 1);
            int src2 = src0 + 2;
            float s00 = __shfl_sync(0xffffffffu, acc[nb][0], src0);
            float s01 = __shfl_sync(0xffffffffu, acc[nb][1], src0);
            float s20 = __shfl_sync(0xffffffffu, acc[nb][0], src2);
            float s21 = __shfl_sync(0xffffffffu, acc[nb][1], src2);
            float s10 = __shfl_sync(0xffffffffu, acc[nb][2], src0);
            float s11 = __shfl_sync(0xffffffffu, acc[nb][3], src0);
            float s30 = __shfl_sync(0xffffffffu, acc[nb][2], src2);
            float s31 = __shfl_sync(0xffffffffu, acc[nb][3], src2);
            bool odd = (t & 1);
            float pa0 = odd ? s01 : s00;
            float pa1 = odd ? s11 : s10;
            float pa2 = odd ? s21 : s20;
            float pa3 = odd ? s31 : s30;
            uint32_t ah[4], al[4];
            split_tf32(pa0, ah[0], al[0]);
            split_tf32(pa1, ah[1], al[1]);
            split_tf32(pa2, ah[2], al[2]);
            split_tf32(pa3, ah[3], al[3]);
            int srow = sw + nb * 8;
#pragma unroll
            for (int n = 0; n < 8; n++) {
                uint32_t bv[2];
                bv[0] = Vhu[(srow + t) * PVV + n * 8 + g];
                bv[1] = Vhu[(srow + t + 4) * PVV + n * 8 + g];
                mma_tf32(O[n], ah, bv);
                mma_tf32(O[n], al, bv);
            }
        }
    }

    // ---- merge the two s-halves (once per CTA), then write out
    __syncthreads();           // main loop done; smem free for reuse
    const int r0l = wm * 16 + g, r1l = r0l + 8;
    float* Ob = Qh;            // pitch 66, 64x66 fits in Qh
    if (!ARMA) {
        float* ml = Kh;        // [64][4]: m0,l0 (wn=0), m1,l1 (wn=1)
        if (t == 0) {
            ml[r0l * 4 + wn * 2 + 0] = m_run[0];
            ml[r0l * 4 + wn * 2 + 1] = l_run[0];
            ml[r1l * 4 + wn * 2 + 0] = m_run[1];
            ml[r1l * 4 + wn * 2 + 1] = l_run[1];
        }
        __syncthreads();
        float ma0 = ml[r0l * 4 + 0], la0 = ml[r0l * 4 + 1];
        float mb0 = ml[r0l * 4 + 2], lb0 = ml[r0l * 4 + 3];
        float ma1 = ml[r1l * 4 + 0], la1 = ml[r1l * 4 + 1];
        float mb1 = ml[r1l * 4 + 2], lb1 = ml[r1l * 4 + 3];
        float mm0 = fmaxf(ma0, mb0), mm1 = fmaxf(ma1, mb1);
        float lt0 = la0 * __expf(ma0 - mm0) + lb0 * __expf(mb0 - mm0);
        float lt1 = la1 * __expf(ma1 - mm1) + lb1 * __expf(mb1 - mm1);
        float f0 = __expf(m_run[0] - mm0);
        float f1 = __expf(m_run[1] - mm1);
#pragma unroll
        for (int n = 0; n < 8; n++) {
            O[n][0] *= f0; O[n][1] *= f0;
            O[n][2] *= f1; O[n][3] *= f1;
        }
        if (wn == 1) {
#pragma unroll
            for (int n = 0; n < 8; n++) {
                int col = n * 8 + 2 * t;
                *(float2*)(Ob + r0l * 66 + col) = make_float2(O[n][0], O[n][1]);
                *(float2*)(Ob + r1l * 66 + col) = make_float2(O[n][2], O[n][3]);
            }
        }
        __syncthreads();
        if (wn == 0) {
            float inv0 = 1.f / lt0, inv1 = 1.f / lt1;
            float* yo = g_y + (size_t)bh * TT * HD;
#pragma unroll
            for (int n = 0; n < 8; n++) {
                int col = n * 8 + 2 * t;
                float2 p0 = *(const float2*)(Ob + r0l * 66 + col);
                float2 p1 = *(const float2*)(Ob + r1l * 66 + col);
                *(float2*)(yo + (size_t)qrow0 * HD + col) =
                    make_float2((O[n][0] + p0.x) * inv0, (O[n][1] + p0.y) * inv0);
                *(float2*)(yo + (size_t)qrow1 * HD + col) =
                    make_float2((O[n][2] + p1.x) * inv1, (O[n][3] + p1.y) * inv1);
            }
        }
    } else {
        if (wn == 1) {
#pragma unroll
            for (int n = 0; n < 8; n++) {
                int col = n * 8 + 2 * t;
                *(float2*)(Ob + r0l * 66 + col) = make_float2(O[n][0], O[n][1]);
                *(float2*)(Ob + r1l * 66 + col) = make_float2(O[n][2], O[n][3]);
            }
        }
        __syncthreads();
        if (wn == 0) {
            float* yo = g_ysum + (size_t)b * TT * TC + h * HD;
#pragma unroll
            for (int n = 0; n < 8; n++) {
                int col = n * 8 + 2 * t;
                float2 p0 = *(const float2*)(Ob + r0l * 66 + col);
                float2 p1 = *(const float2*)(Ob + r1l * 66 + col);
                float2 y0 = *(const float2*)(yb + (size_t)qrow0 * HD + col);
                float2 y1 = *(const float2*)(yb + (size_t)qrow1 * HD + col);
                *(float2*)(yo + (size_t)qrow0 * TC + col) =
                    make_float2(O[n][0] + p0.x + y0.x, O[n][1] + p0.y + y0.y);
                *(float2*)(yo + (size_t)qrow1 * TC + col) =
                    make_float2(O[n][2] + p1.x + y1.x, O[n][3] + p1.y + y1.y);
            }
        }
    }
}

// ---------------------------------------------------------------------------
extern "C" void kernel_launch(void* const* d_in, const int* in_sizes, int n_in,
                              void* d_out, int out_size)
{
    (void)in_sizes; (void)n_in; (void)out_size;
    const float* x      = (const float*)d_in[0];
    const float* W_attn = (const float*)d_in[1];
    const float* W_k2   = (const float*)d_in[2];
    const float* W_proj = (const float*)d_in[3];
    float* out = (float*)d_out;

    const int smem_attn = (4 * 64 * PQ + 64 * PVV) * (int)sizeof(float); // 88064
    cudaFuncSetAttribute(fattn_kernel<0>,
                         cudaFuncAttributeMaxDynamicSharedMemorySize, smem_attn);
    cudaFuncSetAttribute(fattn_kernel<1>,
                         cudaFuncAttributeMaxDynamicSharedMemorySize, smem_attn);

    dim3 blk(256);
    tgemm_kernel<0><<<dim3(2 * TC / 128, MROWS / 128), blk>>>(
        x, W_attn, nullptr, MROWS, 2 * TC, TC);
    tgemm_kernel<1><<<dim3(TC / 128, MROWS / 128), blk>>>(
        x, W_k2, nullptr, MROWS, TC, TC);
    fattn_kernel<0><<<dim3(TT / 64, BHN), 256, smem_attn>>>(x);
    fattn_kernel<1><<<dim3(TT / 64, BHN), 256, smem_attn>>>(x);
    tgemm_kernel<2><<<dim3(TC / 128, MROWS / 128), blk>>>(
        nullptr, W_proj, out, MROWS, TC, TC);
}

// round 5
// speedup vs baseline: 2.7702x; 1.1094x over previous
#include <cuda_runtime.h>
#include <math.h>
#include <stdint.h>

#define TB 2
#define TT 2048
#define TC 1024
#define NH 16
#define HD 64
#define BHN (TB*NH)
#define MROWS (TB*TT)
#define SCALE 0.125f

#define PQ 68   // pitch for Q/K tiles
#define PVV 72  // pitch for V/E tiles

#define NELEM ((size_t)BHN*TT*HD)

// Scratch: pre-transformed tf32 operands in head layout [b*NH+h][t][64]
__device__ uint32_t g_qsh[NELEM], g_qsl[NELEM];   // q*scale hi/lo
__device__ uint32_t g_qah[NELEM], g_qal[NELEM];   // qa hi/lo
__device__ uint32_t g_kh [NELEM], g_kl [NELEM];   // k hi/lo
__device__ uint32_t g_kah[NELEM], g_kal[NELEM];   // ka hi/lo
__device__ uint32_t g_v32[NELEM];                 // tf32(x) head layout
__device__ uint32_t g_e32[NELEM];                 // tf32(x[s+1]-y[s])
__device__ float    g_y  [NELEM];
__device__ float    g_ysum[(size_t)TB*TT*TC];

__device__ __forceinline__ uint32_t f2tf32(float f) {
    uint32_t u;
    asm volatile("cvt.rna.tf32.f32 %0, %1;" : "=r"(u) : "f"(f));
    return u;
}
__device__ __forceinline__ void split_tf32(float v, uint32_t& hi, uint32_t& lo) {
    hi = f2tf32(v);
    lo = f2tf32(v - __uint_as_float(hi));
}
__device__ __forceinline__ void mma_tf32(float c[4], const uint32_t a[4],
                                         const uint32_t b[2]) {
    asm volatile(
        "mma.sync.aligned.m16n8k8.row.col.f32.tf32.tf32.f32 "
        "{%0,%1,%2,%3}, {%4,%5,%6,%7}, {%8,%9}, {%0,%1,%2,%3};"
        : "+f"(c[0]), "+f"(c[1]), "+f"(c[2]), "+f"(c[3])
        : "r"(a[0]), "r"(a[1]), "r"(a[2]), "r"(a[3]), "r"(b[0]), "r"(b[1]));
}
__device__ __forceinline__ uint32_t s2u(const void* p) {
    return (uint32_t)__cvta_generic_to_shared(p);
}
__device__ __forceinline__ void cp_async16(uint32_t dst, const void* src) {
    asm volatile("cp.async.cg.shared.global [%0], [%1], 16;"
                 :: "r"(dst), "l"(src));
}
#define CP_COMMIT() asm volatile("cp.async.commit_group;")
#define CP_WAIT0()  asm volatile("cp.async.wait_group 0;" ::: "memory")

// ---------------------------------------------------------------------------
// prep: v32 = tf32(x) gathered into head layout
// ---------------------------------------------------------------------------
__global__ __launch_bounds__(256)
void prep_v32_kernel(const float* __restrict__ x)
{
    size_t i = (((size_t)blockIdx.x * 256 + threadIdx.x) << 2);
    int d  = (int)(i & 63);
    int t  = (int)((i >> 6) & (TT - 1));
    int bh = (int)(i >> 17);
    int b = bh >> 4, h = bh & 15;
    float4 v = *(const float4*)(x + ((size_t)b * TT + t) * TC + h * 64 + d);
    *(uint4*)(g_v32 + i) =
        make_uint4(f2tf32(v.x), f2tf32(v.y), f2tf32(v.z), f2tf32(v.w));
}

// ---------------------------------------------------------------------------
// TF32 tensor-core GEMM. Epilogues fold the attention operand transforms:
// MODE 0: x@W_attn -> qsh/qsl, qah/qal (n<TC) and kh/kl (n>=TC), head layout
// MODE 1: x@W_k2   -> kah/kal (sigmoid transform), head layout
// MODE 2: g_ysum @ W_proj -> Cout
// ---------------------------------------------------------------------------
template<int MODE>
__global__ __launch_bounds__(256)
void tgemm_kernel(const float* __restrict__ A, const float* __restrict__ Bw,
                  float* __restrict__ Cout, int M, int N, int K)
{
    __shared__ uint32_t As[16][136];
    __shared__ uint32_t Bs[16][136];

    const int tid = threadIdx.x;
    const int lane = tid & 31;
    const int warp = tid >> 5;
    const int warpM = warp >> 2;
    const int warpN = warp & 3;
    const int g = lane >> 2;
    const int t = lane & 3;

    const int bm = blockIdx.y * 128;
    const int bn = blockIdx.x * 128;
    const float* Ap = (MODE == 2) ? (const float*)g_ysum : A;

    float acc[4][4][4];
#pragma unroll
    for (int i = 0; i < 4; i++)
#pragma unroll
        for (int j = 0; j < 4; j++)
#pragma unroll
            for (int r = 0; r < 4; r++) acc[i][j][r] = 0.f;

    const int aRow0 = tid >> 2,            aq0 = (tid & 3) << 2;
    const int aRow1 = (tid + 256) >> 2,    aq1 = aq0;
    const int bRow0 = tid >> 5,            bc0 = (tid & 31) << 2;
    const int bRow1 = (tid + 256) >> 5,    bc1 = bc0;

    float4 pa0, pa1, pb0, pb1;
    pa0 = *(const float4*)(Ap + (size_t)(bm + aRow0) * K + aq0);
    pa1 = *(const float4*)(Ap + (size_t)(bm + aRow1) * K + aq1);
    pb0 = *(const float4*)(Bw + (size_t)(bRow0) * N + bn + bc0);
    pb1 = *(const float4*)(Bw + (size_t)(bRow1) * N + bn + bc1);

    for (int kt = 0; kt < K; kt += 16) {
        __syncthreads();
        As[aq0 + 0][aRow0] = f2tf32(pa0.x);
        As[aq0 + 1][aRow0] = f2tf32(pa0.y);
        As[aq0 + 2][aRow0] = f2tf32(pa0.z);
        As[aq0 + 3][aRow0] = f2tf32(pa0.w);
        As[aq1 + 0][aRow1] = f2tf32(pa1.x);
        As[aq1 + 1][aRow1] = f2tf32(pa1.y);
        As[aq1 + 2][aRow1] = f2tf32(pa1.z);
        As[aq1 + 3][aRow1] = f2tf32(pa1.w);
        Bs[bRow0][bc0 + 0] = f2tf32(pb0.x);
        Bs[bRow0][bc0 + 1] = f2tf32(pb0.y);
        Bs[bRow0][bc0 + 2] = f2tf32(pb0.z);
        Bs[bRow0][bc0 + 3] = f2tf32(pb0.w);
        Bs[bRow1][bc1 + 0] = f2tf32(pb1.x);
        Bs[bRow1][bc1 + 1] = f2tf32(pb1.y);
        Bs[bRow1][bc1 + 2] = f2tf32(pb1.z);
        Bs[bRow1][bc1 + 3] = f2tf32(pb1.w);
        __syncthreads();

        if (kt + 16 < K) {
            int kn = kt + 16;
            pa0 = *(const float4*)(Ap + (size_t)(bm + aRow0) * K + kn + aq0);
            pa1 = *(const float4*)(Ap + (size_t)(bm + aRow1) * K + kn + aq1);
            pb0 = *(const float4*)(Bw + (size_t)(kn + bRow0) * N + bn + bc0);
            pb1 = *(const float4*)(Bw + (size_t)(kn + bRow1) * N + bn + bc1);
        }

#pragma unroll
        for (int ks = 0; ks < 2; ks++) {
            const int k0 = ks * 8;
            uint32_t af[4][4], bf[4][2];
#pragma unroll
            for (int i = 0; i < 4; i++) {
                int m0 = warpM * 64 + i * 16;
                af[i][0] = As[k0 + t][m0 + g];
                af[i][1] = As[k0 + t][m0 + g + 8];
                af[i][2] = As[k0 + t + 4][m0 + g];
                af[i][3] = As[k0 + t + 4][m0 + g + 8];
            }
#pragma unroll
            for (int j = 0; j < 4; j++) {
                int n0 = warpN * 32 + j * 8;
                bf[j][0] = Bs[k0 + t][n0 + g];
                bf[j][1] = Bs[k0 + t + 4][n0 + g];
            }
#pragma unroll
            for (int i = 0; i < 4; i++)
#pragma unroll
                for (int j = 0; j < 4; j++)
                    mma_tf32(acc[i][j], af[i], bf[j]);
        }
    }

#pragma unroll
    for (int i = 0; i < 4; i++) {
#pragma unroll
        for (int j = 0; j < 4; j++) {
            int col = bn + warpN * 32 + j * 8 + t * 2;
#pragma unroll
            for (int half = 0; half < 2; half++) {
                int m = bm + warpM * 64 + i * 16 + g + half * 8;
                float2 v = half == 0 ? make_float2(acc[i][j][0], acc[i][j][1])
                                     : make_float2(acc[i][j][2], acc[i][j][3]);
                if (MODE == 2) {
                    *(float2*)(Cout + (size_t)m * N + col) = v;
                } else {
                    int b = m >> 11;
                    int tt = m & (TT - 1);
                    uint32_t h0, l0, h1, l1;
                    if (MODE == 0) {
                        if (col < TC) {
                            int h = col >> 6, dd = col & 63;
                            size_t off =
                                (((size_t)(b * NH + h) * TT + tt) << 6) + dd;
                            float q0 = v.x * SCALE, q1 = v.y * SCALE;
                            split_tf32(q0, h0, l0); split_tf32(q1, h1, l1);
                            *(uint2*)(g_qsh + off) = make_uint2(h0, h1);
                            *(uint2*)(g_qsl + off) = make_uint2(l0, l1);
                            float a0 = fminf(q0, 0.02f * q0);
                            float a1 = fminf(q1, 0.02f * q1);
                            split_tf32(a0, h0, l0); split_tf32(a1, h1, l1);
                            *(uint2*)(g_qah + off) = make_uint2(h0, h1);
                            *(uint2*)(g_qal + off) = make_uint2(l0, l1);
                        } else {
                            int nn = col - TC;
                            int h = nn >> 6, dd = nn & 63;
                            size_t off =
                                (((size_t)(b * NH + h) * TT + tt) << 6) + dd;
                            split_tf32(v.x, h0, l0); split_tf32(v.y, h1, l1);
                            *(uint2*)(g_kh + off) = make_uint2(h0, h1);
                            *(uint2*)(g_kl + off) = make_uint2(l0, l1);
                        }
                    } else {
                        int h = col >> 6, dd = col & 63;
                        size_t off =
                            (((size_t)(b * NH + h) * TT + tt) << 6) + dd;
                        float ka0 = 1.f / (1.f + __expf(-0.0025f * v.x));
                        float ka1 = 1.f / (1.f + __expf(-0.0025f * v.y));
                        split_tf32(ka0, h0, l0); split_tf32(ka1, h1, l1);
                        *(uint2*)(g_kah + off) = make_uint2(h0, h1);
                        *(uint2*)(g_kal + off) = make_uint2(l0, l1);
                    }
                }
            }
        }
    }
}

// ---------------------------------------------------------------------------
// Fused tensor-core attention, 256 threads (8 warps), 64x64 tiles.
// All operands pre-transformed tf32 in global -> staging is pure cp.async.
// Warp (wm, wn): q-rows [wm*16,+16), s-cols [wn*32,+32); warp-local online
// softmax, halves merged once at the end. attn0 epilogue also emits e32.
// ---------------------------------------------------------------------------
template<int ARMA>
__global__ __launch_bounds__(256)
void fattn_kernel(const float* __restrict__ x)
{
    extern __shared__ float sm[];
    float* Qh = sm;                   // [64][PQ]
    float* Ql = Qh + 64 * PQ;
    float* Kh = Ql + 64 * PQ;
    float* Kl = Kh + 64 * PQ;
    float* Vh = Kl + 64 * PQ;         // [64][PVV]

    const int tid = threadIdx.x;
    const int lane = tid & 31;
    const int warp = tid >> 5;
    const int wm = warp >> 1;
    const int wn = warp & 1;
    const int g = lane >> 2;
    const int t = lane & 3;

    const int bh = blockIdx.y;
    const int b = bh >> 4, h = bh & 15;
    const int qb = (int)gridDim.x - 1 - (int)blockIdx.x;  // heavy first
    const int q0 = qb * 64;

    const uint32_t* qh_g = (ARMA ? g_qah : g_qsh) + (size_t)bh * TT * HD;
    const uint32_t* ql_g = (ARMA ? g_qal : g_qsl) + (size_t)bh * TT * HD;
    const uint32_t* kh_g = (ARMA ? g_kah : g_kh) + (size_t)bh * TT * HD;
    const uint32_t* kl_g = (ARMA ? g_kal : g_kl) + (size_t)bh * TT * HD;
    const uint32_t* v_g  = (ARMA ? g_e32 : g_v32) + (size_t)bh * TT * HD;
    const float* yb = g_y + (size_t)bh * TT * HD;
    const float* vx = x + (size_t)b * TT * TC + h * HD;

    const int lr = tid >> 4;
    const int lc4 = (tid & 15) << 2;

    const uint32_t Qh_s = s2u(Qh), Ql_s = s2u(Ql);
    const uint32_t Kh_s = s2u(Kh), Kl_s = s2u(Kl), Vh_s = s2u(Vh);

    // ---- stage Q (joins first tile's cp.async group)
#pragma unroll
    for (int it = 0; it < 4; it++) {
        int r = lr + it * 16;
        cp_async16(Qh_s + (r * PQ + lc4) * 4, qh_g + (size_t)(q0 + r) * HD + lc4);
        cp_async16(Ql_s + (r * PQ + lc4) * 4, ql_g + (size_t)(q0 + r) * HD + lc4);
    }

    float O[8][4];
#pragma unroll
    for (int n = 0; n < 8; n++)
#pragma unroll
        for (int c = 0; c < 4; c++) O[n][c] = 0.f;
    float m_run[2] = {-1e30f, -1e30f};
    float l_run[2] = {0.f, 0.f};

    const int qrow0 = q0 + wm * 16 + g;
    const int qrow1 = qrow0 + 8;
    const int sw = wn * 32;
    const int mr = wm * 16 + g;

    const uint32_t* Qhu = (const uint32_t*)Qh;
    const uint32_t* Qlu = (const uint32_t*)Ql;
    const uint32_t* Khu = (const uint32_t*)Kh;
    const uint32_t* Klu = (const uint32_t*)Kl;
    const uint32_t* Vhu = (const uint32_t*)Vh;

    for (int kt = 0; kt <= qb; kt++) {
        const int s0 = kt * 64;
        __syncthreads();   // previous tile's readers done

        // ---- stage K hi/lo + V/E (pure copies)
#pragma unroll
        for (int it = 0; it < 4; it++) {
            int r = lr + it * 16;
            size_t s = (size_t)(s0 + r) * HD + lc4;
            cp_async16(Kh_s + (r * PQ + lc4) * 4, kh_g + s);
            cp_async16(Kl_s + (r * PQ + lc4) * 4, kl_g + s);
            cp_async16(Vh_s + (r * PVV + lc4) * 4, v_g + s);
        }
        CP_COMMIT();
        CP_WAIT0();
        __syncthreads();

        // ---- S = Q @ K^T over this warp's 32 s-cols (3xTF32)
        float acc[4][4];
#pragma unroll
        for (int nb = 0; nb < 4; nb++)
#pragma unroll
            for (int c = 0; c < 4; c++) acc[nb][c] = 0.f;

#pragma unroll
        for (int k0 = 0; k0 < 64; k0 += 8) {
            uint32_t ah[4], al[4];
            ah[0] = Qhu[mr * PQ + k0 + t];
            ah[1] = Qhu[(mr + 8) * PQ + k0 + t];
            ah[2] = Qhu[mr * PQ + k0 + t + 4];
            ah[3] = Qhu[(mr + 8) * PQ + k0 + t + 4];
            al[0] = Qlu[mr * PQ + k0 + t];
            al[1] = Qlu[(mr + 8) * PQ + k0 + t];
            al[2] = Qlu[mr * PQ + k0 + t + 4];
            al[3] = Qlu[(mr + 8) * PQ + k0 + t + 4];
#pragma unroll
            for (int nb = 0; nb < 4; nb++) {
                int sr = sw + nb * 8 + g;
                uint32_t bh2[2], bl2[2];
                bh2[0] = Khu[sr * PQ + k0 + t];
                bh2[1] = Khu[sr * PQ + k0 + t + 4];
                bl2[0] = Klu[sr * PQ + k0 + t];
                bl2[1] = Klu[sr * PQ + k0 + t + 4];
                mma_tf32(acc[nb], ah, bh2);
                mma_tf32(acc[nb], al, bh2);
                mma_tf32(acc[nb], ah, bl2);
            }
        }

        const bool diag = (kt == qb);
        if (diag) {
#pragma unroll
            for (int nb = 0; nb < 4; nb++) {
                int colb = s0 + sw + nb * 8 + 2 * t;
#pragma unroll
                for (int c = 0; c < 4; c++) {
                    int cc = colb + (c & 1);
                    int rr = (c >= 2) ? qrow1 : qrow0;
                    if (ARMA) { if (cc >= rr) acc[nb][c] = 0.f; }
                    else      { if (cc >  rr) acc[nb][c] = -1e30f; }
                }
            }
        }

        if (!ARMA) {
            float mt0 = -1e30f, mt1 = -1e30f;
#pragma unroll
            for (int nb = 0; nb < 4; nb++) {
                mt0 = fmaxf(mt0, fmaxf(acc[nb][0], acc[nb][1]));
                mt1 = fmaxf(mt1, fmaxf(acc[nb][2], acc[nb][3]));
            }
#pragma unroll
            for (int off = 1; off <= 2; off <<= 1) {
                mt0 = fmaxf(mt0, __shfl_xor_sync(0xffffffffu, mt0, off));
                mt1 = fmaxf(mt1, __shfl_xor_sync(0xffffffffu, mt1, off));
            }
            float mn0 = fmaxf(m_run[0], mt0);
            float mn1 = fmaxf(m_run[1], mt1);
            float corr0 = __expf(m_run[0] - mn0);
            float corr1 = __expf(m_run[1] - mn1);
            m_run[0] = mn0; m_run[1] = mn1;

            float ls0 = 0.f, ls1 = 0.f;
#pragma unroll
            for (int nb = 0; nb < 4; nb++) {
                float p0 = __expf(acc[nb][0] - mn0);
                float p1 = __expf(acc[nb][1] - mn0);
                float p2 = __expf(acc[nb][2] - mn1);
                float p3 = __expf(acc[nb][3] - mn1);
                if (diag) {
                    int colb = s0 + sw + nb * 8 + 2 * t;
                    if (colb     > qrow0) p0 = 0.f;
                    if (colb + 1 > qrow0) p1 = 0.f;
                    if (colb     > qrow1) p2 = 0.f;
                    if (colb + 1 > qrow1) p3 = 0.f;
                }
                acc[nb][0] = p0; acc[nb][1] = p1;
                acc[nb][2] = p2; acc[nb][3] = p3;
                ls0 += p0 + p1;
                ls1 += p2 + p3;
            }
#pragma unroll
            for (int off = 1; off <= 2; off <<= 1) {
                ls0 += __shfl_xor_sync(0xffffffffu, ls0, off);
                ls1 += __shfl_xor_sync(0xffffffffu, ls1, off);
            }
            l_run[0] = l_run[0] * corr0 + ls0;
            l_run[1] = l_run[1] * corr1 + ls1;
#pragma unroll
            for (int n = 0; n < 8; n++) {
                O[n][0] *= corr0; O[n][1] *= corr0;
                O[n][2] *= corr1; O[n][3] *= corr1;
            }
        }

        // ---- O += P @ V : P via shfl (no smem, no syncs)
#pragma unroll
        for (int nb = 0; nb < 4; nb++) {
            int src0 = (lane & ~3) | (t >> 1);
            int src2 = src0 + 2;
            float s00 = __shfl_sync(0xffffffffu, acc[nb][0], src0);
            float s01 = __shfl_sync(0xffffffffu, acc[nb][1], src0);
            float s20 = __shfl_sync(0xffffffffu, acc[nb][0], src2);
            float s21 = __shfl_sync(0xffffffffu, acc[nb][1], src2);
            float s10 = __shfl_sync(0xffffffffu, acc[nb][2], src0);
            float s11 = __shfl_sync(0xffffffffu, acc[nb][3], src0);
            float s30 = __shfl_sync(0xffffffffu, acc[nb][2], src2);
            float s31 = __shfl_sync(0xffffffffu, acc[nb][3], src2);
            bool odd = (t & 1);
            float pa0 = odd ? s01 : s00;
            float pa1 = odd ? s11 : s10;
            float pa2 = odd ? s21 : s20;
            float pa3 = odd ? s31 : s30;
            uint32_t ah[4], al[4];
            split_tf32(pa0, ah[0], al[0]);
            split_tf32(pa1, ah[1], al[1]);
            split_tf32(pa2, ah[2], al[2]);
            split_tf32(pa3, ah[3], al[3]);
            int srow = sw + nb * 8;
#pragma unroll
            for (int n = 0; n < 8; n++) {
                uint32_t bv[2];
                bv[0] = Vhu[(srow + t) * PVV + n * 8 + g];
                bv[1] = Vhu[(srow + t + 4) * PVV + n * 8 + g];
                mma_tf32(O[n], ah, bv);
                mma_tf32(O[n], al, bv);
            }
        }
    }

    // ---- merge s-halves once, write out
    __syncthreads();
    const int r0l = wm * 16 + g, r1l = r0l + 8;
    float* Ob = Qh;            // reuse smem, pitch 66
    if (!ARMA) {
        float* ml = Kh;
        if (t == 0) {
            ml[r0l * 4 + wn * 2 + 0] = m_run[0];
            ml[r0l * 4 + wn * 2 + 1] = l_run[0];
            ml[r1l * 4 + wn * 2 + 0] = m_run[1];
            ml[r1l * 4 + wn * 2 + 1] = l_run[1];
        }
        __syncthreads();
        float ma0 = ml[r0l * 4 + 0], la0 = ml[r0l * 4 + 1];
        float mb0 = ml[r0l * 4 + 2], lb0 = ml[r0l * 4 + 3];
        float ma1 = ml[r1l * 4 + 0], la1 = ml[r1l * 4 + 1];
        float mb1 = ml[r1l * 4 + 2], lb1 = ml[r1l * 4 + 3];
        float mm0 = fmaxf(ma0, mb0), mm1 = fmaxf(ma1, mb1);
        float lt0 = la0 * __expf(ma0 - mm0) + lb0 * __expf(mb0 - mm0);
        float lt1 = la1 * __expf(ma1 - mm1) + lb1 * __expf(mb1 - mm1);
        float f0 = __expf(m_run[0] - mm0);
        float f1 = __expf(m_run[1] - mm1);
#pragma unroll
        for (int n = 0; n < 8; n++) {
            O[n][0] *= f0; O[n][1] *= f0;
            O[n][2] *= f1; O[n][3] *= f1;
        }
        if (wn == 1) {
#pragma unroll
            for (int n = 0; n < 8; n++) {
                int col = n * 8 + 2 * t;
                *(float2*)(Ob + r0l * 66 + col) = make_float2(O[n][0], O[n][1]);
                *(float2*)(Ob + r1l * 66 + col) = make_float2(O[n][2], O[n][3]);
            }
        }
        __syncthreads();
        if (wn == 0) {
            float inv0 = 1.f / lt0, inv1 = 1.f / lt1;
            float* yo = g_y + (size_t)bh * TT * HD;
            uint32_t* eo = g_e32 + (size_t)bh * TT * HD;
#pragma unroll
            for (int n = 0; n < 8; n++) {
                int col = n * 8 + 2 * t;
                float2 p0 = *(const float2*)(Ob + r0l * 66 + col);
                float2 p1 = *(const float2*)(Ob + r1l * 66 + col);
                float y00 = (O[n][0] + p0.x) * inv0;
                float y01 = (O[n][1] + p0.y) * inv0;
                float y10 = (O[n][2] + p1.x) * inv1;
                float y11 = (O[n][3] + p1.y) * inv1;
                *(float2*)(yo + (size_t)qrow0 * HD + col) = make_float2(y00, y01);
                *(float2*)(yo + (size_t)qrow1 * HD + col) = make_float2(y10, y11);
                // e32[s] = tf32(x[s+1] - y[s]); row TT-1 -> 0
                float e00 = 0.f, e01 = 0.f, e10 = 0.f, e11 = 0.f;
                if (qrow0 + 1 < TT) {
                    float2 xv = *(const float2*)(vx + (size_t)(qrow0 + 1) * TC + col);
                    e00 = xv.x - y00; e01 = xv.y - y01;
                }
                if (qrow1 + 1 < TT) {
                    float2 xv = *(const float2*)(vx + (size_t)(qrow1 + 1) * TC + col);
                    e10 = xv.x - y10; e11 = xv.y - y11;
                }
                *(uint2*)(eo + (size_t)qrow0 * HD + col) =
                    make_uint2(f2tf32(e00), f2tf32(e01));
                *(uint2*)(eo + (size_t)qrow1 * HD + col) =
                    make_uint2(f2tf32(e10), f2tf32(e11));
            }
        }
    } else {
        if (wn == 1) {
#pragma unroll
            for (int n = 0; n < 8; n++) {
                int col = n * 8 + 2 * t;
                *(float2*)(Ob + r0l * 66 + col) = make_float2(O[n][0], O[n][1]);
                *(float2*)(Ob + r1l * 66 + col) = make_float2(O[n][2], O[n][3]);
            }
        }
        __syncthreads();
        if (wn == 0) {
            float* yo = g_ysum + (size_t)b * TT * TC + h * HD;
#pragma unroll
            for (int n = 0; n < 8; n++) {
                int col = n * 8 + 2 * t;
                float2 p0 = *(const float2*)(Ob + r0l * 66 + col);
                float2 p1 = *(const float2*)(Ob + r1l * 66 + col);
                float2 y0 = *(const float2*)(yb + (size_t)qrow0 * HD + col);
                float2 y1 = *(const float2*)(yb + (size_t)qrow1 * HD + col);
                *(float2*)(yo + (size_t)qrow0 * TC + col) =
                    make_float2(O[n][0] + p0.x + y0.x, O[n][1] + p0.y + y0.y);
                *(float2*)(yo + (size_t)qrow1 * TC + col) =
                    make_float2(O[n][2] + p1.x + y1.x, O[n][3] + p1.y + y1.y);
            }
        }
    }
}

// ---------------------------------------------------------------------------
extern "C" void kernel_launch(void* const* d_in, const int* in_sizes, int n_in,
                              void* d_out, int out_size)
{
    (void)in_sizes; (void)n_in; (void)out_size;
    const float* x      = (const float*)d_in[0];
    const float* W_attn = (const float*)d_in[1];
    const float* W_k2   = (const float*)d_in[2];
    const float* W_proj = (const float*)d_in[3];
    float* out = (float*)d_out;

    const int smem_attn = (4 * 64 * PQ + 64 * PVV) * (int)sizeof(float); // 88064
    cudaFuncSetAttribute(fattn_kernel<0>,
                         cudaFuncAttributeMaxDynamicSharedMemorySize, smem_attn);
    cudaFuncSetAttribute(fattn_kernel<1>,
                         cudaFuncAttributeMaxDynamicSharedMemorySize, smem_attn);

    dim3 blk(256);
    prep_v32_kernel<<<(int)(NELEM / 4 / 256), 256>>>(x);
    tgemm_kernel<0><<<dim3(2 * TC / 128, MROWS / 128), blk>>>(
        x, W_attn, nullptr, MROWS, 2 * TC, TC);
    tgemm_kernel<1><<<dim3(TC / 128, MROWS / 128), blk>>>(
        x, W_k2, nullptr, MROWS, TC, TC);
    fattn_kernel<0><<<dim3(TT / 64, BHN), 256, smem_attn>>>(x);
    fattn_kernel<1><<<dim3(TT / 64, BHN), 256, smem_attn>>>(x);
    tgemm_kernel<2><<<dim3(TC / 128, MROWS / 128), blk>>>(
        nullptr, W_proj, out, MROWS, TC, TC);
}